// round 14
// baseline (speedup 1.0000x reference)
#include <cuda_runtime.h>
#include <cuda_fp16.h>
#include <cstdint>

#define Bn 256
#define Qn 16
#define Sn 512
#define Mn 8
#define Dn 128
#define NT 512
#define TILE 64
#define NCHUNK 8
#define PPITCH 520
#define CGP 132
#define TPITCH 272   // bytes per row in fp16 [s][d] / [q][d] tiles

typedef unsigned long long ull;

// ---- shared memory layout (float offsets) ----
#define OFF_QT   0          // qT[128][16]
#define OFF_P    2048       // p[16][520]
#define OFF_W    10368      // w[512]
#define OFF_OUT  10880      // out [q][128]
#define OFF_KBAR 12928      // kbar [q][128]
#define OFF_OCG  14976      // cg out [q][128]
#define OFF_KBCG 17024      // cg kbar [q][128]
#define OFF_KCG  19072      // kcg[8][132]
#define OFF_VCG  20128      // vcg[8][132]
#define OFF_PCG  21184      // p_cg[16][8]
#define OFF_WCG  21312      // w_cg[8]
#define OFF_RED  21320      // 16 warps * 4 = 64
// phase-B fp16 [s][d] tiles: 64 rows x 272B = 4352 floats each
#define OFF_VH   29696
#define OFF_VL   34048
#define OFF_KH   38400
#define OFF_WKH  42752
#define OFF_PH   47104      // p fp16 [16 q][64 s] = 512 floats, 128B rows swizzled
#define OFF_PL   47616
// scores-phase: SK tiles [128 s][272B] = 8704 floats each (alias phase-B tiles)
#define OFF_SKH  29696      // covers VH+VL
#define OFF_SKL  38400      // covers KH+WKH
#define OFF_QH   48128      // Q fp16 hi [16 q][272B] = 1088 floats
#define OFF_QL   49216
#define SMEM_FLOATS 50304   // 201216 bytes

__device__ float g_losses[Bn];
__device__ unsigned int g_count;

__device__ __forceinline__ float clip50(float x) {
    return fminf(fmaxf(x, -50.0f), 50.0f);
}
__device__ __forceinline__ ull dup2(float x) {
    ull r; asm("mov.b64 %0, {%1, %1};" : "=l"(r) : "f"(x)); return r;
}
__device__ __forceinline__ ull fma2(ull a, ull b, ull c) {
    ull d; asm("fma.rn.f32x2 %0, %1, %2, %3;" : "=l"(d) : "l"(a), "l"(b), "l"(c)); return d;
}
__device__ __forceinline__ float2 unpack2(ull p) {
    float2 f; asm("mov.b64 {%0, %1}, %2;" : "=f"(f.x), "=f"(f.y) : "l"(p)); return f;
}
__device__ __forceinline__ uint32_t smem_u32(const void* p) {
    uint32_t a;
    asm("{ .reg .u64 t; cvta.to.shared.u64 t, %1; cvt.u32.u64 %0, t; }" : "=r"(a) : "l"(p));
    return a;
}
__device__ __forceinline__ void split2h(float f0, float f1, uint32_t& hi, uint32_t& lo) {
    __half2 h = __floats2half2_rn(f0, f1);
    float2 hf = __half22float2(h);
    __half2 l = __floats2half2_rn(f0 - hf.x, f1 - hf.y);
    hi = *(uint32_t*)&h;
    lo = *(uint32_t*)&l;
}
__device__ __forceinline__ uint32_t cvt2h(float f0, float f1) {
    __half2 h = __floats2half2_rn(f0, f1);
    return *(uint32_t*)&h;
}
__device__ __forceinline__ uint32_t swz(uint32_t off) { return off ^ ((off >> 3) & 0x70); }

__device__ __forceinline__ void ldsm4(uint32_t& r0, uint32_t& r1, uint32_t& r2, uint32_t& r3, uint32_t a) {
    asm volatile("ldmatrix.sync.aligned.m8n8.x4.shared.b16 {%0,%1,%2,%3}, [%4];"
                 : "=r"(r0), "=r"(r1), "=r"(r2), "=r"(r3) : "r"(a));
}
__device__ __forceinline__ void ldsm4t(uint32_t& r0, uint32_t& r1, uint32_t& r2, uint32_t& r3, uint32_t a) {
    asm volatile("ldmatrix.sync.aligned.m8n8.x4.trans.shared.b16 {%0,%1,%2,%3}, [%4];"
                 : "=r"(r0), "=r"(r1), "=r"(r2), "=r"(r3) : "r"(a));
}
__device__ __forceinline__ void mma16816(float* d, const uint32_t* a, uint32_t b0, uint32_t b1) {
    asm volatile("mma.sync.aligned.m16n8k16.row.col.f32.f16.f16.f32 "
                 "{%0,%1,%2,%3}, {%4,%5,%6,%7}, {%8,%9}, {%0,%1,%2,%3};"
                 : "+f"(d[0]), "+f"(d[1]), "+f"(d[2]), "+f"(d[3])
                 : "r"(a[0]), "r"(a[1]), "r"(a[2]), "r"(a[3]), "r"(b0), "r"(b1));
}

__global__ void __launch_bounds__(NT, 1)
fml_kernel(const float* __restrict__ gq, const float* __restrict__ gk,
           const float* __restrict__ gv, const float* __restrict__ gkcg,
           const float* __restrict__ gvcg, float* __restrict__ gout)
{
    extern __shared__ float sm[];
    char* smc = (char*)sm;
    const int b   = blockIdx.x;
    const int tid = threadIdx.x;
    const int wid = tid >> 5, lane = tid & 31;
    const float scale = 0.088388347648318447f;
    const uint32_t smb = smem_u32(sm);

    // ldmatrix lane geometry
    const int grp = lane >> 3, li = lane & 7;
    const int arow = (grp & 1) * 8 + li;
    const int akc  = (grp >> 1) * 8;
    const int asrow = (grp >> 1) * 8 + li;
    const int ascol = (grp & 1) * 8;
    const int bsrow = (grp & 1) * 8 + li;
    const int bscol = (grp >> 1) * 8;
    const int brow = (grp >> 1) * 8 + li;
    const int bkc  = (grp & 1) * 8;

    // ---- load qT, stage Q fp16, load cg tensors ----
    const float* qb = gq + (size_t)b * Qn * Dn;
    for (int i = tid; i < Qn * Dn; i += NT) {
        int qq = i >> 7, d = i & 127;
        sm[OFF_QT + d * 16 + qq] = qb[i];
    }
    if (tid < 256) {
        int q = tid >> 4, dblk = tid & 15;
        const float* src = qb + q * Dn + dblk * 8;
        float4 f0 = *(const float4*)src;
        float4 f1 = *(const float4*)(src + 4);
        uint4 qh, ql;
        uint32_t h, l;
        split2h(f0.x, f0.y, h, l); qh.x = h; ql.x = l;
        split2h(f0.z, f0.w, h, l); qh.y = h; ql.y = l;
        split2h(f1.x, f1.y, h, l); qh.z = h; ql.z = l;
        split2h(f1.z, f1.w, h, l); qh.w = h; ql.w = l;
        uint32_t off = (uint32_t)(q * TPITCH + dblk * 16);
        *(uint4*)(smc + OFF_QH * 4 + off) = qh;
        *(uint4*)(smc + OFF_QL * 4 + off) = ql;
    }
    const float* kcb = gkcg + (size_t)b * Mn * Dn;
    const float* vcb = gvcg + (size_t)b * Mn * Dn;
    for (int i = tid; i < Mn * Dn; i += NT) {
        int j = i >> 7, d = i & 127;
        sm[OFF_KCG + j * CGP + d] = kcb[i];
        sm[OFF_VCG + j * CGP + d] = vcb[i];
    }
    __syncthreads();

    // ---- cg scores / softmax / w_cg / out / kbar (exact SIMT) ----
    if (tid < Qn * Mn) {
        int qq = tid >> 3, j = tid & 7;
        float acc = 0.f;
        #pragma unroll 8
        for (int d = 0; d < Dn; ++d)
            acc = fmaf(sm[OFF_QT + d * 16 + qq], sm[OFF_KCG + j * CGP + d], acc);
        sm[OFF_PCG + qq * Mn + j] = acc * scale;
    }
    __syncthreads();
    if (tid < Qn) {
        float m = -1e30f;
        #pragma unroll
        for (int j = 0; j < Mn; ++j) m = fmaxf(m, sm[OFF_PCG + tid * Mn + j]);
        float ss = 0.f;
        #pragma unroll
        for (int j = 0; j < Mn; ++j) {
            float e = __expf(sm[OFF_PCG + tid * Mn + j] - m);
            sm[OFF_PCG + tid * Mn + j] = e; ss += e;
        }
        float inv = 1.f / ss;
        #pragma unroll
        for (int j = 0; j < Mn; ++j) sm[OFF_PCG + tid * Mn + j] *= inv;
    }
    __syncthreads();
    if (tid < Mn) {
        float a = 0.f;
        #pragma unroll
        for (int qq = 0; qq < Qn; ++qq) a += sm[OFF_PCG + qq * Mn + tid];
        sm[OFF_WCG + tid] = a;
    }
    if (tid < 256) {
        int qq = tid >> 4, dblk = tid & 15;
        ull o2[4], kb2[4];
        #pragma unroll
        for (int i = 0; i < 4; ++i) { o2[i] = 0ull; kb2[i] = 0ull; }
        #pragma unroll
        for (int j = 0; j < Mn; ++j) {
            ull pc2 = dup2(sm[OFF_PCG + qq * Mn + j]);
            ulonglong2 vA = *(const ulonglong2*)&sm[OFF_VCG + j * CGP + dblk * 8];
            ulonglong2 vB = *(const ulonglong2*)&sm[OFF_VCG + j * CGP + dblk * 8 + 4];
            ulonglong2 kA = *(const ulonglong2*)&sm[OFF_KCG + j * CGP + dblk * 8];
            ulonglong2 kB = *(const ulonglong2*)&sm[OFF_KCG + j * CGP + dblk * 8 + 4];
            o2[0]  = fma2(pc2, vA.x, o2[0]);  o2[1]  = fma2(pc2, vA.y, o2[1]);
            o2[2]  = fma2(pc2, vB.x, o2[2]);  o2[3]  = fma2(pc2, vB.y, o2[3]);
            kb2[0] = fma2(pc2, kA.x, kb2[0]); kb2[1] = fma2(pc2, kA.y, kb2[1]);
            kb2[2] = fma2(pc2, kB.x, kb2[2]); kb2[3] = fma2(pc2, kB.y, kb2[3]);
        }
        *(ulonglong2*)&sm[OFF_OCG  + qq * Dn + dblk * 8]     = make_ulonglong2(o2[0], o2[1]);
        *(ulonglong2*)&sm[OFF_OCG  + qq * Dn + dblk * 8 + 4] = make_ulonglong2(o2[2], o2[3]);
        *(ulonglong2*)&sm[OFF_KBCG + qq * Dn + dblk * 8]     = make_ulonglong2(kb2[0], kb2[1]);
        *(ulonglong2*)&sm[OFF_KBCG + qq * Dn + dblk * 8 + 4] = make_ulonglong2(kb2[2], kb2[3]);
    }

    // ---- dense scores via HMMA: 4 double-chunks of 128 s, all 16 warps ----
    const float* kbase = gk + (size_t)b * Sn * Dn;
    const float* vbase = gv + (size_t)b * Sn * Dn;
    const int r  = lane >> 2;
    const int cq = (lane & 3) * 2;
    const int ps  = tid >> 4;        // staging row base (0..31)
    const int pdb = tid & 15;        // staging dblk

    float4 sk[8];
    #pragma unroll
    for (int it = 0; it < 4; ++it) {
        const float* kp = kbase + (size_t)(ps + it * 32) * Dn + pdb * 8;
        sk[it * 2]     = *(const float4*)kp;
        sk[it * 2 + 1] = *(const float4*)(kp + 4);
    }
    for (int t = 0; t < 4; ++t) {
        __syncthreads();
        #pragma unroll
        for (int it = 0; it < 4; ++it) {
            int s = ps + it * 32;
            float4 k0 = sk[it * 2], k1 = sk[it * 2 + 1];
            uint4 kh, kl;
            uint32_t h, l;
            split2h(k0.x, k0.y, h, l); kh.x = h; kl.x = l;
            split2h(k0.z, k0.w, h, l); kh.y = h; kl.y = l;
            split2h(k1.x, k1.y, h, l); kh.z = h; kl.z = l;
            split2h(k1.z, k1.w, h, l); kh.w = h; kl.w = l;
            uint32_t off = (uint32_t)(s * TPITCH + pdb * 16);
            *(uint4*)(smc + OFF_SKH * 4 + off) = kh;
            *(uint4*)(smc + OFF_SKL * 4 + off) = kl;
        }
        if (t + 1 < 4) {
            #pragma unroll
            for (int it = 0; it < 4; ++it) {
                const float* kp = kbase + (size_t)((t + 1) * 128 + ps + it * 32) * Dn + pdb * 8;
                sk[it * 2]     = *(const float4*)kp;
                sk[it * 2 + 1] = *(const float4*)(kp + 4);
            }
        }
        __syncthreads();
        {
            int mw8 = wid & 7;       // s-tile: 16 rows at mw8*16 within 128
            int qj = wid >> 3;       // q-half
            float accS[4] = {0.f, 0.f, 0.f, 0.f};
            #pragma unroll
            for (int k = 0; k < 8; ++k) {
                uint32_t ah[4], al[4], qh[4], qlr[4];
                uint32_t aoff = (uint32_t)((mw8 * 16 + arow) * TPITCH + (k * 16 + akc) * 2);
                ldsm4(ah[0], ah[1], ah[2], ah[3], smb + OFF_SKH * 4 + aoff);
                ldsm4(al[0], al[1], al[2], al[3], smb + OFF_SKL * 4 + aoff);
                uint32_t boff = (uint32_t)(brow * TPITCH + (k * 16 + bkc) * 2);
                ldsm4(qh[0], qh[1], qh[2], qh[3], smb + OFF_QH * 4 + boff);
                ldsm4(qlr[0], qlr[1], qlr[2], qlr[3], smb + OFF_QL * 4 + boff);
                int bs = qj * 2;
                mma16816(accS, ah, qh[bs], qh[bs + 1]);
                mma16816(accS, ah, qlr[bs], qlr[bs + 1]);
                mma16816(accS, al, qh[bs], qh[bs + 1]);
            }
            int sb = t * 128 + mw8 * 16;
            int q0 = qj * 8 + cq;
            sm[OFF_P + q0 * PPITCH + sb + r]           = accS[0] * scale;
            sm[OFF_P + (q0 + 1) * PPITCH + sb + r]     = accS[1] * scale;
            sm[OFF_P + q0 * PPITCH + sb + r + 8]       = accS[2] * scale;
            sm[OFF_P + (q0 + 1) * PPITCH + sb + r + 8] = accS[3] * scale;
        }
    }
    __syncthreads();

    // ---- softmax: one row per warp ----
    {
        float* row = &sm[OFF_P + wid * PPITCH];
        float m = -1e30f;
        #pragma unroll
        for (int i = 0; i < 16; ++i) m = fmaxf(m, row[lane + 32 * i]);
        #pragma unroll
        for (int o = 16; o > 0; o >>= 1) m = fmaxf(m, __shfl_xor_sync(0xffffffffu, m, o));
        float ss = 0.f;
        float ev[16];
        #pragma unroll
        for (int i = 0; i < 16; ++i) { ev[i] = __expf(row[lane + 32 * i] - m); ss += ev[i]; }
        #pragma unroll
        for (int o = 16; o > 0; o >>= 1) ss += __shfl_xor_sync(0xffffffffu, ss, o);
        float inv = 1.f / ss;
        #pragma unroll
        for (int i = 0; i < 16; ++i) row[lane + 32 * i] = ev[i] * inv;
    }
    __syncthreads();
    {
        int s = tid;
        float a = 0.f;
        #pragma unroll
        for (int qq = 0; qq < Qn; ++qq) a += sm[OFF_P + qq * PPITCH + s];
        sm[OFF_W + s] = a;
    }

    // ---- main tensor-core pass (pipelined K/V prefetch) ----
    const int mw   = wid & 7;
    const int m0   = mw * 16;
    const int nj   = wid >> 3;

    float accJ[8][4];
    float accO[2][4];
    #pragma unroll
    for (int nt = 0; nt < 8; ++nt)
        #pragma unroll
        for (int e = 0; e < 4; ++e) accJ[nt][e] = 0.f;
    #pragma unroll
    for (int nt = 0; nt < 2; ++nt)
        #pragma unroll
        for (int e = 0; e < 4; ++e) accO[nt][e] = 0.f;

    float4 pk[4], pv[4];
    {
        const float* k0p = kbase + (size_t)ps * Dn + pdb * 8;
        const float* k1p = kbase + (size_t)(ps + 32) * Dn + pdb * 8;
        const float* v0p = vbase + (size_t)ps * Dn + pdb * 8;
        const float* v1p = vbase + (size_t)(ps + 32) * Dn + pdb * 8;
        pk[0] = *(const float4*)k0p; pk[1] = *(const float4*)(k0p + 4);
        pk[2] = *(const float4*)k1p; pk[3] = *(const float4*)(k1p + 4);
        pv[0] = *(const float4*)v0p; pv[1] = *(const float4*)(v0p + 4);
        pv[2] = *(const float4*)v1p; pv[3] = *(const float4*)(v1p + 4);
    }

    for (int c = 0; c < NCHUNK; ++c) {
        const int s0 = c * TILE;
        __syncthreads();
        #pragma unroll
        for (int it = 0; it < 2; ++it) {
            int s = ps + it * 32;
            float4 k0 = pk[it * 2], k1 = pk[it * 2 + 1];
            float4 v0 = pv[it * 2], v1 = pv[it * 2 + 1];
            float ws = sm[OFF_W + s0 + s];
            uint32_t off = (uint32_t)(s * TPITCH + pdb * 16);
            *(uint4*)(smc + OFF_KH * 4 + off) =
                make_uint4(cvt2h(k0.x, k0.y), cvt2h(k0.z, k0.w),
                           cvt2h(k1.x, k1.y), cvt2h(k1.z, k1.w));
            *(uint4*)(smc + OFF_WKH * 4 + off) =
                make_uint4(cvt2h(k0.x * ws, k0.y * ws), cvt2h(k0.z * ws, k0.w * ws),
                           cvt2h(k1.x * ws, k1.y * ws), cvt2h(k1.z * ws, k1.w * ws));
            uint4 vh, vl;
            uint32_t h, l;
            split2h(v0.x, v0.y, h, l); vh.x = h; vl.x = l;
            split2h(v0.z, v0.w, h, l); vh.y = h; vl.y = l;
            split2h(v1.x, v1.y, h, l); vh.z = h; vl.z = l;
            split2h(v1.z, v1.w, h, l); vh.w = h; vl.w = l;
            *(uint4*)(smc + OFF_VH * 4 + off) = vh;
            *(uint4*)(smc + OFF_VL * 4 + off) = vl;
        }
        {
            int qq = wid;
            float p0 = sm[OFF_P + qq * PPITCH + s0 + 2 * lane];
            float p1 = sm[OFF_P + qq * PPITCH + s0 + 2 * lane + 1];
            uint32_t sw = swz((uint32_t)(qq * 128 + lane * 4));
            uint32_t hi, lo;
            split2h(p0, p1, hi, lo);
            *(uint32_t*)(smc + OFF_PH * 4 + sw) = hi;
            *(uint32_t*)(smc + OFF_PL * 4 + sw) = lo;
        }
        if (c + 1 < NCHUNK) {
            const float* k0p = kbase + (size_t)((c + 1) * TILE + ps) * Dn + pdb * 8;
            const float* k1p = kbase + (size_t)((c + 1) * TILE + ps + 32) * Dn + pdb * 8;
            const float* v0p = vbase + (size_t)((c + 1) * TILE + ps) * Dn + pdb * 8;
            const float* v1p = vbase + (size_t)((c + 1) * TILE + ps + 32) * Dn + pdb * 8;
            pk[0] = *(const float4*)k0p; pk[1] = *(const float4*)(k0p + 4);
            pk[2] = *(const float4*)k1p; pk[3] = *(const float4*)(k1p + 4);
            pv[0] = *(const float4*)v0p; pv[1] = *(const float4*)(v0p + 4);
            pv[2] = *(const float4*)v1p; pv[3] = *(const float4*)(v1p + 4);
        }
        __syncthreads();

        #pragma unroll
        for (int k = 0; k < 4; ++k) {
            uint32_t vah[4], valo[4];
            uint32_t aoff = (uint32_t)((k * 16 + asrow) * TPITCH + (m0 + ascol) * 2);
            ldsm4t(vah[0], vah[1], vah[2], vah[3], smb + OFF_VH * 4 + aoff);
            ldsm4t(valo[0], valo[1], valo[2], valo[3], smb + OFF_VL * 4 + aoff);

            uint32_t ph[4], pl[4];
            uint32_t pa = swz((uint32_t)(brow * 128 + (k * 16 + bkc) * 2));
            ldsm4(ph[0], ph[1], ph[2], ph[3], smb + OFF_PH * 4 + pa);
            ldsm4(pl[0], pl[1], pl[2], pl[3], smb + OFF_PL * 4 + pa);

            if (nj == 0) {
                mma16816(accO[0], vah, ph[0], ph[1]);
                mma16816(accO[0], vah, pl[0], pl[1]);
                mma16816(accO[0], valo, ph[0], ph[1]);
                mma16816(accO[1], vah, ph[2], ph[3]);
                mma16816(accO[1], vah, pl[2], pl[3]);
                mma16816(accO[1], valo, ph[2], ph[3]);
            } else {
                uint32_t kah[4];
                ldsm4t(kah[0], kah[1], kah[2], kah[3], smb + OFF_KH * 4 + aoff);
                mma16816(accO[0], kah, ph[0], ph[1]);
                mma16816(accO[0], kah, pl[0], pl[1]);
                mma16816(accO[1], kah, ph[2], ph[3]);
                mma16816(accO[1], kah, pl[2], pl[3]);
            }
            #pragma unroll
            for (int np = 0; np < 4; ++np) {
                uint32_t bh[4];
                uint32_t ba = (uint32_t)((k * 16 + bsrow) * TPITCH +
                                         (nj * 64 + np * 16 + bscol) * 2);
                ldsm4t(bh[0], bh[1], bh[2], bh[3], smb + OFF_WKH * 4 + ba);
                mma16816(accJ[np * 2], vah, bh[0], bh[1]);
                mma16816(accJ[np * 2], valo, bh[0], bh[1]);
                mma16816(accJ[np * 2 + 1], vah, bh[2], bh[3]);
                mma16816(accJ[np * 2 + 1], valo, bh[2], bh[3]);
            }
        }
    }
    __syncthreads();

    // ---- write out^T (nj==0) / kbar^T (nj==1) to smem [q][d] ----
    {
        int base = (nj == 0) ? OFF_OUT : OFF_KBAR;
        #pragma unroll
        for (int nt = 0; nt < 2; ++nt) {
            int qq = nt * 8 + cq;
            sm[base + qq * Dn + m0 + r]           = accO[nt][0];
            sm[base + (qq + 1) * Dn + m0 + r]     = accO[nt][1];
            sm[base + qq * Dn + m0 + r + 8]       = accO[nt][2];
            sm[base + (qq + 1) * Dn + m0 + r + 8] = accO[nt][3];
        }
    }
    __syncthreads();

    // ---- epilogue: J2 + cg jacobian + clip + cosine ----
    float o0a[16], o1a[16], c0a[16], c1a[16], vc0[8], vc1[8];
    #pragma unroll
    for (int q = 0; q < 16; ++q) {
        o0a[q] = sm[OFF_OUT + q * Dn + m0 + r];
        o1a[q] = sm[OFF_OUT + q * Dn + m0 + r + 8];
        c0a[q] = sm[OFF_OCG + q * Dn + m0 + r];
        c1a[q] = sm[OFF_OCG + q * Dn + m0 + r + 8];
    }
    #pragma unroll
    for (int j = 0; j < 8; ++j) {
        float wc = sm[OFF_WCG + j];
        vc0[j] = wc * sm[OFF_VCG + j * CGP + m0 + r];
        vc1[j] = wc * sm[OFF_VCG + j * CGP + m0 + r + 8];
    }

    float dd = 0.f, ccv = 0.f, dc = 0.f;
    #pragma unroll
    for (int nt = 0; nt < 8; ++nt) {
        ull jd0, jd1, jc0, jc1;
        asm("mov.b64 %0, {%1, %2};" : "=l"(jd0) : "f"(accJ[nt][0]), "f"(accJ[nt][1]));
        asm("mov.b64 %0, {%1, %2};" : "=l"(jd1) : "f"(accJ[nt][2]), "f"(accJ[nt][3]));
        jc0 = 0ull; jc1 = 0ull;
        int colb = nj * 64 + nt * 8 + cq;
        #pragma unroll
        for (int q = 0; q < 16; ++q) {
            ull kbp = *(const ull*)&sm[OFF_KBAR + q * Dn + colb];
            jd0 = fma2(dup2(-o0a[q]), kbp, jd0);
            jd1 = fma2(dup2(-o1a[q]), kbp, jd1);
        }
        #pragma unroll
        for (int j = 0; j < 8; ++j) {
            ull kcp = *(const ull*)&sm[OFF_KCG + j * CGP + colb];
            jc0 = fma2(dup2(vc0[j]), kcp, jc0);
            jc1 = fma2(dup2(vc1[j]), kcp, jc1);
        }
        #pragma unroll
        for (int q = 0; q < 16; ++q) {
            ull kbp = *(const ull*)&sm[OFF_KBCG + q * Dn + colb];
            jc0 = fma2(dup2(-c0a[q]), kbp, jc0);
            jc1 = fma2(dup2(-c1a[q]), kbp, jc1);
        }
        float2 d0 = unpack2(jd0), d1 = unpack2(jd1);
        float2 g0 = unpack2(jc0), g1 = unpack2(jc1);
        float jdv[4] = {d0.x, d0.y, d1.x, d1.y};
        float jcv[4] = {g0.x, g0.y, g1.x, g1.y};
        #pragma unroll
        for (int e = 0; e < 4; ++e) {
            float a = clip50(jdv[e] * scale);
            float g = clip50(jcv[e] * scale);
            dd  = fmaf(a, a, dd);
            ccv = fmaf(g, g, ccv);
            dc  = fmaf(a, g, dc);
        }
    }
    float cons = 0.f;
    #pragma unroll
    for (int i = 0; i < 4; ++i) {
        float dif = sm[OFF_OUT + tid * 4 + i] - sm[OFF_OCG + tid * 4 + i];
        cons = fmaf(dif, dif, cons);
    }

    #pragma unroll
    for (int o = 16; o > 0; o >>= 1) {
        dd   += __shfl_xor_sync(0xffffffffu, dd,   o);
        ccv  += __shfl_xor_sync(0xffffffffu, ccv,  o);
        dc   += __shfl_xor_sync(0xffffffffu, dc,   o);
        cons += __shfl_xor_sync(0xffffffffu, cons, o);
    }
    if (lane == 0) {
        sm[OFF_RED + wid * 4 + 0] = dd;
        sm[OFF_RED + wid * 4 + 1] = ccv;
        sm[OFF_RED + wid * 4 + 2] = dc;
        sm[OFF_RED + wid * 4 + 3] = cons;
    }
    __syncthreads();
    if (tid == 0) {
        float DD = 0.f, CC = 0.f, DC = 0.f, CO = 0.f;
        #pragma unroll
        for (int w8 = 0; w8 < 16; ++w8) {
            DD += sm[OFF_RED + w8 * 4 + 0];
            CC += sm[OFF_RED + w8 * 4 + 1];
            DC += sm[OFF_RED + w8 * 4 + 2];
            CO += sm[OFF_RED + w8 * 4 + 3];
        }
        float cosv = DC / (sqrtf(DD) * sqrtf(CC) + 1e-8f);
        g_losses[b] = (1.0f - cosv) + CO * (1.0f / (float)(Qn * Dn));
    }

    // ---- fused final reduction: last CTA sums g_losses (fixed order) ----
    if (wid == 0) {
        unsigned int ticket = 0;
        if (lane == 0) {
            __threadfence();
            ticket = atomicInc(&g_count, Bn - 1);   // wraps to 0 after Bn arrivals
        }
        ticket = __shfl_sync(0xffffffffu, ticket, 0);
        if (ticket == Bn - 1) {
            float a = 0.f;
            #pragma unroll
            for (int i = 0; i < 8; ++i) a += g_losses[lane * 8 + i];
            #pragma unroll
            for (int o = 16; o > 0; o >>= 1) a += __shfl_xor_sync(0xffffffffu, a, o);
            if (lane == 0) gout[0] = a * (1.0f / (float)Bn);
        }
    }
}

extern "C" void kernel_launch(void* const* d_in, const int* in_sizes, int n_in,
                              void* d_out, int out_size)
{
    const float* q   = (const float*)d_in[0];
    const float* k   = (const float*)d_in[1];
    const float* v   = (const float*)d_in[2];
    const float* kcg = (const float*)d_in[3];
    const float* vcg = (const float*)d_in[4];

    cudaFuncSetAttribute(fml_kernel, cudaFuncAttributeMaxDynamicSharedMemorySize,
                         SMEM_FLOATS * (int)sizeof(float));
    fml_kernel<<<Bn, NT, SMEM_FLOATS * sizeof(float)>>>(q, k, v, kcg, vcg, (float*)d_out);
}

// round 15
// speedup vs baseline: 1.1271x; 1.1271x over previous
#include <cuda_runtime.h>
#include <cuda_fp16.h>
#include <cstdint>

#define Bn 256
#define Qn 16
#define Sn 512
#define Mn 8
#define Dn 128
#define NT 512
#define TILE 64
#define NCHUNK 8
#define PPITCH 520
#define CGP 132
#define TPITCH 272

typedef unsigned long long ull;

// ---- shared memory layout (float offsets) ----
#define OFF_QT   0
#define OFF_P    2048
#define OFF_W    10368
#define OFF_OUT  10880
#define OFF_KBAR 12928
#define OFF_OCG  14976
#define OFF_KBCG 17024
#define OFF_KCG  19072
#define OFF_VCG  20128
#define OFF_PCG  21184
#define OFF_WCG  21312
#define OFF_RED  21320
#define OFF_VH   29696
#define OFF_VL   34048
#define OFF_KH   38400
#define OFF_WKH  42752
#define OFF_PH   47104
#define OFF_PL   47616
#define SMEM_FLOATS 48128
// scores-phase aliases:
#define OFF_SKH  OFF_VH
#define OFF_SKL  OFF_VL
#define OFF_QH   OFF_WKH
#define OFF_QL   (OFF_WKH + 1088)

__device__ float g_losses[Bn];
__device__ unsigned int g_count;

__device__ __forceinline__ float clip50(float x) {
    return fminf(fmaxf(x, -50.0f), 50.0f);
}
__device__ __forceinline__ ull dup2(float x) {
    ull r; asm("mov.b64 %0, {%1, %1};" : "=l"(r) : "f"(x)); return r;
}
__device__ __forceinline__ ull fma2(ull a, ull b, ull c) {
    ull d; asm("fma.rn.f32x2 %0, %1, %2, %3;" : "=l"(d) : "l"(a), "l"(b), "l"(c)); return d;
}
__device__ __forceinline__ float2 unpack2(ull p) {
    float2 f; asm("mov.b64 {%0, %1}, %2;" : "=f"(f.x), "=f"(f.y) : "l"(p)); return f;
}
__device__ __forceinline__ uint32_t smem_u32(const void* p) {
    uint32_t a;
    asm("{ .reg .u64 t; cvta.to.shared.u64 t, %1; cvt.u32.u64 %0, t; }" : "=r"(a) : "l"(p));
    return a;
}
__device__ __forceinline__ void split2h(float f0, float f1, uint32_t& hi, uint32_t& lo) {
    __half2 h = __floats2half2_rn(f0, f1);
    float2 hf = __half22float2(h);
    __half2 l = __floats2half2_rn(f0 - hf.x, f1 - hf.y);
    hi = *(uint32_t*)&h;
    lo = *(uint32_t*)&l;
}
__device__ __forceinline__ uint32_t cvt2h(float f0, float f1) {
    __half2 h = __floats2half2_rn(f0, f1);
    return *(uint32_t*)&h;
}
__device__ __forceinline__ uint32_t swz(uint32_t off) { return off ^ ((off >> 3) & 0x70); }

__device__ __forceinline__ void ldsm4(uint32_t& r0, uint32_t& r1, uint32_t& r2, uint32_t& r3, uint32_t a) {
    asm volatile("ldmatrix.sync.aligned.m8n8.x4.shared.b16 {%0,%1,%2,%3}, [%4];"
                 : "=r"(r0), "=r"(r1), "=r"(r2), "=r"(r3) : "r"(a));
}
__device__ __forceinline__ void ldsm4t(uint32_t& r0, uint32_t& r1, uint32_t& r2, uint32_t& r3, uint32_t a) {
    asm volatile("ldmatrix.sync.aligned.m8n8.x4.trans.shared.b16 {%0,%1,%2,%3}, [%4];"
                 : "=r"(r0), "=r"(r1), "=r"(r2), "=r"(r3) : "r"(a));
}
__device__ __forceinline__ void mma16816(float* d, const uint32_t* a, uint32_t b0, uint32_t b1) {
    asm volatile("mma.sync.aligned.m16n8k16.row.col.f32.f16.f16.f32 "
                 "{%0,%1,%2,%3}, {%4,%5,%6,%7}, {%8,%9}, {%0,%1,%2,%3};"
                 : "+f"(d[0]), "+f"(d[1]), "+f"(d[2]), "+f"(d[3])
                 : "r"(a[0]), "r"(a[1]), "r"(a[2]), "r"(a[3]), "r"(b0), "r"(b1));
}

__global__ void __launch_bounds__(NT, 1)
fml_kernel(const float* __restrict__ gq, const float* __restrict__ gk,
           const float* __restrict__ gv, const float* __restrict__ gkcg,
           const float* __restrict__ gvcg, float* __restrict__ gout)
{
    extern __shared__ float sm[];
    char* smc = (char*)sm;
    const int b   = blockIdx.x;
    const int tid = threadIdx.x;
    const int wid = tid >> 5, lane = tid & 31;
    const float scale = 0.088388347648318447f;
    const uint32_t smb = smem_u32(sm);

    // ldmatrix lane geometry
    const int grp = lane >> 3, li = lane & 7;
    const int arow = (grp & 1) * 8 + li;
    const int akc  = (grp >> 1) * 8;
    const int asrow = (grp >> 1) * 8 + li;
    const int ascol = (grp & 1) * 8;
    const int bsrow = (grp & 1) * 8 + li;
    const int bscol = (grp >> 1) * 8;
    const int brow = (grp >> 1) * 8 + li;
    const int bkc  = (grp & 1) * 8;

    // ---- load qT, stage Q fp16, load cg tensors ----
    const float* qb = gq + (size_t)b * Qn * Dn;
    for (int i = tid; i < Qn * Dn; i += NT) {
        int qq = i >> 7, d = i & 127;
        sm[OFF_QT + d * 16 + qq] = qb[i];
    }
    if (tid < 256) {
        int q = tid >> 4, dblk = tid & 15;
        const float* src = qb + q * Dn + dblk * 8;
        float4 f0 = *(const float4*)src;
        float4 f1 = *(const float4*)(src + 4);
        uint4 qh, ql;
        uint32_t h, l;
        split2h(f0.x, f0.y, h, l); qh.x = h; ql.x = l;
        split2h(f0.z, f0.w, h, l); qh.y = h; ql.y = l;
        split2h(f1.x, f1.y, h, l); qh.z = h; ql.z = l;
        split2h(f1.z, f1.w, h, l); qh.w = h; ql.w = l;
        uint32_t off = (uint32_t)(q * TPITCH + dblk * 16);
        *(uint4*)(smc + OFF_QH * 4 + off) = qh;
        *(uint4*)(smc + OFF_QL * 4 + off) = ql;
    }
    const float* kcb = gkcg + (size_t)b * Mn * Dn;
    const float* vcb = gvcg + (size_t)b * Mn * Dn;
    for (int i = tid; i < Mn * Dn; i += NT) {
        int j = i >> 7, d = i & 127;
        sm[OFF_KCG + j * CGP + d] = kcb[i];
        sm[OFF_VCG + j * CGP + d] = vcb[i];
    }
    __syncthreads();

    // ---- cg scores / softmax / w_cg / out / kbar (exact SIMT) ----
    if (tid < Qn * Mn) {
        int qq = tid >> 3, j = tid & 7;
        float acc = 0.f;
        #pragma unroll 8
        for (int d = 0; d < Dn; ++d)
            acc = fmaf(sm[OFF_QT + d * 16 + qq], sm[OFF_KCG + j * CGP + d], acc);
        sm[OFF_PCG + qq * Mn + j] = acc * scale;
    }
    __syncthreads();
    if (tid < Qn) {
        float m = -1e30f;
        #pragma unroll
        for (int j = 0; j < Mn; ++j) m = fmaxf(m, sm[OFF_PCG + tid * Mn + j]);
        float ss = 0.f;
        #pragma unroll
        for (int j = 0; j < Mn; ++j) {
            float e = __expf(sm[OFF_PCG + tid * Mn + j] - m);
            sm[OFF_PCG + tid * Mn + j] = e; ss += e;
        }
        float inv = 1.f / ss;
        #pragma unroll
        for (int j = 0; j < Mn; ++j) sm[OFF_PCG + tid * Mn + j] *= inv;
    }
    __syncthreads();
    if (tid < Mn) {
        float a = 0.f;
        #pragma unroll
        for (int qq = 0; qq < Qn; ++qq) a += sm[OFF_PCG + qq * Mn + tid];
        sm[OFF_WCG + tid] = a;
    }
    if (tid < 256) {
        int qq = tid >> 4, dblk = tid & 15;
        ull o2[4], kb2[4];
        #pragma unroll
        for (int i = 0; i < 4; ++i) { o2[i] = 0ull; kb2[i] = 0ull; }
        #pragma unroll
        for (int j = 0; j < Mn; ++j) {
            ull pc2 = dup2(sm[OFF_PCG + qq * Mn + j]);
            ulonglong2 vA = *(const ulonglong2*)&sm[OFF_VCG + j * CGP + dblk * 8];
            ulonglong2 vB = *(const ulonglong2*)&sm[OFF_VCG + j * CGP + dblk * 8 + 4];
            ulonglong2 kA = *(const ulonglong2*)&sm[OFF_KCG + j * CGP + dblk * 8];
            ulonglong2 kB = *(const ulonglong2*)&sm[OFF_KCG + j * CGP + dblk * 8 + 4];
            o2[0]  = fma2(pc2, vA.x, o2[0]);  o2[1]  = fma2(pc2, vA.y, o2[1]);
            o2[2]  = fma2(pc2, vB.x, o2[2]);  o2[3]  = fma2(pc2, vB.y, o2[3]);
            kb2[0] = fma2(pc2, kA.x, kb2[0]); kb2[1] = fma2(pc2, kA.y, kb2[1]);
            kb2[2] = fma2(pc2, kB.x, kb2[2]); kb2[3] = fma2(pc2, kB.y, kb2[3]);
        }
        *(ulonglong2*)&sm[OFF_OCG  + qq * Dn + dblk * 8]     = make_ulonglong2(o2[0], o2[1]);
        *(ulonglong2*)&sm[OFF_OCG  + qq * Dn + dblk * 8 + 4] = make_ulonglong2(o2[2], o2[3]);
        *(ulonglong2*)&sm[OFF_KBCG + qq * Dn + dblk * 8]     = make_ulonglong2(kb2[0], kb2[1]);
        *(ulonglong2*)&sm[OFF_KBCG + qq * Dn + dblk * 8 + 4] = make_ulonglong2(kb2[2], kb2[3]);
    }

    // ---- dense scores via HMMA (pipelined K prefetch, R13 layout) ----
    const float* kbase = gk + (size_t)b * Sn * Dn;
    const float* vbase = gv + (size_t)b * Sn * Dn;
    const int r  = lane >> 2;
    const int cq = (lane & 3) * 2;
    const int ps  = tid >> 4;
    const int pdb = tid & 15;

    float4 sk[4];
    {
        const float* k0p = kbase + (size_t)ps * Dn + pdb * 8;
        const float* k1p = kbase + (size_t)(ps + 32) * Dn + pdb * 8;
        sk[0] = *(const float4*)k0p; sk[1] = *(const float4*)(k0p + 4);
        sk[2] = *(const float4*)k1p; sk[3] = *(const float4*)(k1p + 4);
    }
    for (int t = 0; t < NCHUNK; ++t) {
        __syncthreads();
        #pragma unroll
        for (int it = 0; it < 2; ++it) {
            int s = ps + it * 32;
            float4 k0 = sk[it * 2], k1 = sk[it * 2 + 1];
            uint4 kh, kl;
            uint32_t h, l;
            split2h(k0.x, k0.y, h, l); kh.x = h; kl.x = l;
            split2h(k0.z, k0.w, h, l); kh.y = h; kl.y = l;
            split2h(k1.x, k1.y, h, l); kh.z = h; kl.z = l;
            split2h(k1.z, k1.w, h, l); kh.w = h; kl.w = l;
            uint32_t off = (uint32_t)(s * TPITCH + pdb * 16);
            *(uint4*)(smc + OFF_SKH * 4 + off) = kh;
            *(uint4*)(smc + OFF_SKL * 4 + off) = kl;
        }
        if (t + 1 < NCHUNK) {
            const float* k0p = kbase + (size_t)((t + 1) * TILE + ps) * Dn + pdb * 8;
            const float* k1p = kbase + (size_t)((t + 1) * TILE + ps + 32) * Dn + pdb * 8;
            sk[0] = *(const float4*)k0p; sk[1] = *(const float4*)(k0p + 4);
            sk[2] = *(const float4*)k1p; sk[3] = *(const float4*)(k1p + 4);
        }
        __syncthreads();
        if (wid < 8) {
            int mw = wid & 3;
            int qj = wid >> 2;
            float accS[4] = {0.f, 0.f, 0.f, 0.f};
            #pragma unroll
            for (int k = 0; k < 8; ++k) {
                uint32_t ah[4], al[4], qh[4], qlr[4];
                uint32_t aoff = (uint32_t)((mw * 16 + arow) * TPITCH + (k * 16 + akc) * 2);
                ldsm4(ah[0], ah[1], ah[2], ah[3], smb + OFF_SKH * 4 + aoff);
                ldsm4(al[0], al[1], al[2], al[3], smb + OFF_SKL * 4 + aoff);
                uint32_t boff = (uint32_t)(brow * TPITCH + (k * 16 + bkc) * 2);
                ldsm4(qh[0], qh[1], qh[2], qh[3], smb + OFF_QH * 4 + boff);
                ldsm4(qlr[0], qlr[1], qlr[2], qlr[3], smb + OFF_QL * 4 + boff);
                int bs = qj * 2;
                mma16816(accS, ah, qh[bs], qh[bs + 1]);
                mma16816(accS, ah, qlr[bs], qlr[bs + 1]);
                mma16816(accS, al, qh[bs], qh[bs + 1]);
            }
            int sb = t * TILE + mw * 16;
            int q0 = qj * 8 + cq;
            sm[OFF_P + q0 * PPITCH + sb + r]           = accS[0] * scale;
            sm[OFF_P + (q0 + 1) * PPITCH + sb + r]     = accS[1] * scale;
            sm[OFF_P + q0 * PPITCH + sb + r + 8]       = accS[2] * scale;
            sm[OFF_P + (q0 + 1) * PPITCH + sb + r + 8] = accS[3] * scale;
        }
    }
    __syncthreads();

    // ---- softmax: one row per warp ----
    {
        float* row = &sm[OFF_P + wid * PPITCH];
        float m = -1e30f;
        #pragma unroll
        for (int i = 0; i < 16; ++i) m = fmaxf(m, row[lane + 32 * i]);
        #pragma unroll
        for (int o = 16; o > 0; o >>= 1) m = fmaxf(m, __shfl_xor_sync(0xffffffffu, m, o));
        float ss = 0.f;
        float ev[16];
        #pragma unroll
        for (int i = 0; i < 16; ++i) { ev[i] = __expf(row[lane + 32 * i] - m); ss += ev[i]; }
        #pragma unroll
        for (int o = 16; o > 0; o >>= 1) ss += __shfl_xor_sync(0xffffffffu, ss, o);
        float inv = 1.f / ss;
        #pragma unroll
        for (int i = 0; i < 16; ++i) row[lane + 32 * i] = ev[i] * inv;
    }
    __syncthreads();
    {
        int s = tid;
        float a = 0.f;
        #pragma unroll
        for (int qq = 0; qq < Qn; ++qq) a += sm[OFF_P + qq * PPITCH + s];
        sm[OFF_W + s] = a;
    }

    // ---- main tensor-core pass (pipelined K/V prefetch) ----
    const int mw   = wid & 7;
    const int m0   = mw * 16;
    const int nj   = wid >> 3;

    float accJ[8][4];
    float accO[2][4];
    #pragma unroll
    for (int nt = 0; nt < 8; ++nt)
        #pragma unroll
        for (int e = 0; e < 4; ++e) accJ[nt][e] = 0.f;
    #pragma unroll
    for (int nt = 0; nt < 2; ++nt)
        #pragma unroll
        for (int e = 0; e < 4; ++e) accO[nt][e] = 0.f;

    float4 pk[4], pv[4];
    {
        const float* k0p = kbase + (size_t)ps * Dn + pdb * 8;
        const float* k1p = kbase + (size_t)(ps + 32) * Dn + pdb * 8;
        const float* v0p = vbase + (size_t)ps * Dn + pdb * 8;
        const float* v1p = vbase + (size_t)(ps + 32) * Dn + pdb * 8;
        pk[0] = *(const float4*)k0p; pk[1] = *(const float4*)(k0p + 4);
        pk[2] = *(const float4*)k1p; pk[3] = *(const float4*)(k1p + 4);
        pv[0] = *(const float4*)v0p; pv[1] = *(const float4*)(v0p + 4);
        pv[2] = *(const float4*)v1p; pv[3] = *(const float4*)(v1p + 4);
    }

    for (int c = 0; c < NCHUNK; ++c) {
        const int s0 = c * TILE;
        __syncthreads();
        #pragma unroll
        for (int it = 0; it < 2; ++it) {
            int s = ps + it * 32;
            float4 k0 = pk[it * 2], k1 = pk[it * 2 + 1];
            float4 v0 = pv[it * 2], v1 = pv[it * 2 + 1];
            float ws = sm[OFF_W + s0 + s];
            uint32_t off = (uint32_t)(s * TPITCH + pdb * 16);
            *(uint4*)(smc + OFF_KH * 4 + off) =
                make_uint4(cvt2h(k0.x, k0.y), cvt2h(k0.z, k0.w),
                           cvt2h(k1.x, k1.y), cvt2h(k1.z, k1.w));
            *(uint4*)(smc + OFF_WKH * 4 + off) =
                make_uint4(cvt2h(k0.x * ws, k0.y * ws), cvt2h(k0.z * ws, k0.w * ws),
                           cvt2h(k1.x * ws, k1.y * ws), cvt2h(k1.z * ws, k1.w * ws));
            uint4 vh, vl;
            uint32_t h, l;
            split2h(v0.x, v0.y, h, l); vh.x = h; vl.x = l;
            split2h(v0.z, v0.w, h, l); vh.y = h; vl.y = l;
            split2h(v1.x, v1.y, h, l); vh.z = h; vl.z = l;
            split2h(v1.z, v1.w, h, l); vh.w = h; vl.w = l;
            *(uint4*)(smc + OFF_VH * 4 + off) = vh;
            *(uint4*)(smc + OFF_VL * 4 + off) = vl;
        }
        {
            int qq = wid;
            float p0 = sm[OFF_P + qq * PPITCH + s0 + 2 * lane];
            float p1 = sm[OFF_P + qq * PPITCH + s0 + 2 * lane + 1];
            uint32_t sw = swz((uint32_t)(qq * 128 + lane * 4));
            uint32_t hi, lo;
            split2h(p0, p1, hi, lo);
            *(uint32_t*)(smc + OFF_PH * 4 + sw) = hi;
            *(uint32_t*)(smc + OFF_PL * 4 + sw) = lo;
        }
        if (c + 1 < NCHUNK) {
            const float* k0p = kbase + (size_t)((c + 1) * TILE + ps) * Dn + pdb * 8;
            const float* k1p = kbase + (size_t)((c + 1) * TILE + ps + 32) * Dn + pdb * 8;
            const float* v0p = vbase + (size_t)((c + 1) * TILE + ps) * Dn + pdb * 8;
            const float* v1p = vbase + (size_t)((c + 1) * TILE + ps + 32) * Dn + pdb * 8;
            pk[0] = *(const float4*)k0p; pk[1] = *(const float4*)(k0p + 4);
            pk[2] = *(const float4*)k1p; pk[3] = *(const float4*)(k1p + 4);
            pv[0] = *(const float4*)v0p; pv[1] = *(const float4*)(v0p + 4);
            pv[2] = *(const float4*)v1p; pv[3] = *(const float4*)(v1p + 4);
        }
        __syncthreads();

        #pragma unroll
        for (int k = 0; k < 4; ++k) {
            uint32_t vah[4], valo[4];
            uint32_t aoff = (uint32_t)((k * 16 + asrow) * TPITCH + (m0 + ascol) * 2);
            ldsm4t(vah[0], vah[1], vah[2], vah[3], smb + OFF_VH * 4 + aoff);
            ldsm4t(valo[0], valo[1], valo[2], valo[3], smb + OFF_VL * 4 + aoff);

            uint32_t ph[4], pl[4];
            uint32_t pa = swz((uint32_t)(brow * 128 + (k * 16 + bkc) * 2));
            ldsm4(ph[0], ph[1], ph[2], ph[3], smb + OFF_PH * 4 + pa);
            ldsm4(pl[0], pl[1], pl[2], pl[3], smb + OFF_PL * 4 + pa);

            if (nj == 0) {
                mma16816(accO[0], vah, ph[0], ph[1]);
                mma16816(accO[0], vah, pl[0], pl[1]);
                mma16816(accO[0], valo, ph[0], ph[1]);
                mma16816(accO[1], vah, ph[2], ph[3]);
                mma16816(accO[1], vah, pl[2], pl[3]);
                mma16816(accO[1], valo, ph[2], ph[3]);
            } else {
                uint32_t kah[4];
                ldsm4t(kah[0], kah[1], kah[2], kah[3], smb + OFF_KH * 4 + aoff);
                mma16816(accO[0], kah, ph[0], ph[1]);
                mma16816(accO[0], kah, pl[0], pl[1]);
                mma16816(accO[1], kah, ph[2], ph[3]);
                mma16816(accO[1], kah, pl[2], pl[3]);
            }
            #pragma unroll
            for (int np = 0; np < 4; ++np) {
                uint32_t bh[4];
                uint32_t ba = (uint32_t)((k * 16 + bsrow) * TPITCH +
                                         (nj * 64 + np * 16 + bscol) * 2);
                ldsm4t(bh[0], bh[1], bh[2], bh[3], smb + OFF_WKH * 4 + ba);
                mma16816(accJ[np * 2], vah, bh[0], bh[1]);
                mma16816(accJ[np * 2], valo, bh[0], bh[1]);
                mma16816(accJ[np * 2 + 1], vah, bh[2], bh[3]);
                mma16816(accJ[np * 2 + 1], valo, bh[2], bh[3]);
            }
        }
    }
    __syncthreads();

    // ---- write out^T (nj==0) / kbar^T (nj==1) to smem [q][d] ----
    {
        int base = (nj == 0) ? OFF_OUT : OFF_KBAR;
        #pragma unroll
        for (int nt = 0; nt < 2; ++nt) {
            int qq = nt * 8 + cq;
            sm[base + qq * Dn + m0 + r]           = accO[nt][0];
            sm[base + (qq + 1) * Dn + m0 + r]     = accO[nt][1];
            sm[base + qq * Dn + m0 + r + 8]       = accO[nt][2];
            sm[base + (qq + 1) * Dn + m0 + r + 8] = accO[nt][3];
        }
    }
    __syncthreads();

    // ---- epilogue: J2 + cg jacobian + clip + cosine ----
    float o0a[16], o1a[16], c0a[16], c1a[16], vc0[8], vc1[8];
    #pragma unroll
    for (int q = 0; q < 16; ++q) {
        o0a[q] = sm[OFF_OUT + q * Dn + m0 + r];
        o1a[q] = sm[OFF_OUT + q * Dn + m0 + r + 8];
        c0a[q] = sm[OFF_OCG + q * Dn + m0 + r];
        c1a[q] = sm[OFF_OCG + q * Dn + m0 + r + 8];
    }
    #pragma unroll
    for (int j = 0; j < 8; ++j) {
        float wc = sm[OFF_WCG + j];
        vc0[j] = wc * sm[OFF_VCG + j * CGP + m0 + r];
        vc1[j] = wc * sm[OFF_VCG + j * CGP + m0 + r + 8];
    }

    float dd = 0.f, ccv = 0.f, dc = 0.f;
    #pragma unroll
    for (int nt = 0; nt < 8; ++nt) {
        ull jd0, jd1, jc0, jc1;
        asm("mov.b64 %0, {%1, %2};" : "=l"(jd0) : "f"(accJ[nt][0]), "f"(accJ[nt][1]));
        asm("mov.b64 %0, {%1, %2};" : "=l"(jd1) : "f"(accJ[nt][2]), "f"(accJ[nt][3]));
        jc0 = 0ull; jc1 = 0ull;
        int colb = nj * 64 + nt * 8 + cq;
        #pragma unroll
        for (int q = 0; q < 16; ++q) {
            ull kbp = *(const ull*)&sm[OFF_KBAR + q * Dn + colb];
            jd0 = fma2(dup2(-o0a[q]), kbp, jd0);
            jd1 = fma2(dup2(-o1a[q]), kbp, jd1);
        }
        #pragma unroll
        for (int j = 0; j < 8; ++j) {
            ull kcp = *(const ull*)&sm[OFF_KCG + j * CGP + colb];
            jc0 = fma2(dup2(vc0[j]), kcp, jc0);
            jc1 = fma2(dup2(vc1[j]), kcp, jc1);
        }
        #pragma unroll
        for (int q = 0; q < 16; ++q) {
            ull kbp = *(const ull*)&sm[OFF_KBCG + q * Dn + colb];
            jc0 = fma2(dup2(-c0a[q]), kbp, jc0);
            jc1 = fma2(dup2(-c1a[q]), kbp, jc1);
        }
        float2 d0 = unpack2(jd0), d1 = unpack2(jd1);
        float2 g0 = unpack2(jc0), g1 = unpack2(jc1);
        float jdv[4] = {d0.x, d0.y, d1.x, d1.y};
        float jcv[4] = {g0.x, g0.y, g1.x, g1.y};
        #pragma unroll
        for (int e = 0; e < 4; ++e) {
            float a = clip50(jdv[e] * scale);
            float g = clip50(jcv[e] * scale);
            dd  = fmaf(a, a, dd);
            ccv = fmaf(g, g, ccv);
            dc  = fmaf(a, g, dc);
        }
    }
    float cons = 0.f;
    #pragma unroll
    for (int i = 0; i < 4; ++i) {
        float dif = sm[OFF_OUT + tid * 4 + i] - sm[OFF_OCG + tid * 4 + i];
        cons = fmaf(dif, dif, cons);
    }

    #pragma unroll
    for (int o = 16; o > 0; o >>= 1) {
        dd   += __shfl_xor_sync(0xffffffffu, dd,   o);
        ccv  += __shfl_xor_sync(0xffffffffu, ccv,  o);
        dc   += __shfl_xor_sync(0xffffffffu, dc,   o);
        cons += __shfl_xor_sync(0xffffffffu, cons, o);
    }
    if (lane == 0) {
        sm[OFF_RED + wid * 4 + 0] = dd;
        sm[OFF_RED + wid * 4 + 1] = ccv;
        sm[OFF_RED + wid * 4 + 2] = dc;
        sm[OFF_RED + wid * 4 + 3] = cons;
    }
    __syncthreads();
    if (tid == 0) {
        float DD = 0.f, CC = 0.f, DC = 0.f, CO = 0.f;
        #pragma unroll
        for (int w8 = 0; w8 < 16; ++w8) {
            DD += sm[OFF_RED + w8 * 4 + 0];
            CC += sm[OFF_RED + w8 * 4 + 1];
            DC += sm[OFF_RED + w8 * 4 + 2];
            CO += sm[OFF_RED + w8 * 4 + 3];
        }
        float cosv = DC / (sqrtf(DD) * sqrtf(CC) + 1e-8f);
        g_losses[b] = (1.0f - cosv) + CO * (1.0f / (float)(Qn * Dn));
    }

    // ---- fused final reduction: last CTA sums g_losses (fixed order) ----
    if (wid == 0) {
        unsigned int ticket = 0;
        if (lane == 0) {
            __threadfence();
            ticket = atomicInc(&g_count, Bn - 1);   // wraps to 0 after Bn arrivals
        }
        ticket = __shfl_sync(0xffffffffu, ticket, 0);
        if (ticket == Bn - 1) {
            float a = 0.f;
            #pragma unroll
            for (int i = 0; i < 8; ++i) a += g_losses[lane * 8 + i];
            #pragma unroll
            for (int o = 16; o > 0; o >>= 1) a += __shfl_xor_sync(0xffffffffu, a, o);
            if (lane == 0) gout[0] = a * (1.0f / (float)Bn);
        }
    }
}

extern "C" void kernel_launch(void* const* d_in, const int* in_sizes, int n_in,
                              void* d_out, int out_size)
{
    const float* q   = (const float*)d_in[0];
    const float* k   = (const float*)d_in[1];
    const float* v   = (const float*)d_in[2];
    const float* kcg = (const float*)d_in[3];
    const float* vcg = (const float*)d_in[4];

    cudaFuncSetAttribute(fml_kernel, cudaFuncAttributeMaxDynamicSharedMemorySize,
                         SMEM_FLOATS * (int)sizeof(float));
    fml_kernel<<<Bn, NT, SMEM_FLOATS * sizeof(float)>>>(q, k, v, kcg, vcg, (float*)d_out);
}

// round 16
// speedup vs baseline: 1.1525x; 1.0226x over previous
#include <cuda_runtime.h>
#include <cuda_fp16.h>
#include <cstdint>

#define Bn 256
#define Qn 16
#define Sn 512
#define Mn 8
#define Dn 128
#define NT 512
#define TILE 64
#define NCHUNK 8
#define PPITCH 520
#define CGP 132
#define TPITCH 272

typedef unsigned long long ull;

// ---- shared memory layout (float offsets) ----
#define OFF_QT   0
#define OFF_P    2048
#define OFF_W    10368
#define OFF_OUT  10880
#define OFF_KBAR 12928
#define OFF_OCG  14976
#define OFF_KBCG 17024
#define OFF_KCG  19072
#define OFF_VCG  20128
#define OFF_PCG  21184
#define OFF_WCG  21312
#define OFF_RED  21320
#define OFF_VH   29696
#define OFF_VL   34048
#define OFF_KH   38400
#define OFF_WKH  42752
#define OFF_PH   47104
#define OFF_PL   47616
#define SMEM_FLOATS 48128
// scores-phase aliases:
#define OFF_SKH  OFF_VH
#define OFF_SKL  OFF_VL
#define OFF_QH   OFF_WKH
#define OFF_QL   (OFF_WKH + 1088)

__device__ float g_losses[Bn];
__device__ unsigned int g_count;

__device__ __forceinline__ float clip50(float x) {
    return fminf(fmaxf(x, -50.0f), 50.0f);
}
__device__ __forceinline__ ull dup2(float x) {
    ull r; asm("mov.b64 %0, {%1, %1};" : "=l"(r) : "f"(x)); return r;
}
__device__ __forceinline__ ull fma2(ull a, ull b, ull c) {
    ull d; asm("fma.rn.f32x2 %0, %1, %2, %3;" : "=l"(d) : "l"(a), "l"(b), "l"(c)); return d;
}
__device__ __forceinline__ float2 unpack2(ull p) {
    float2 f; asm("mov.b64 {%0, %1}, %2;" : "=f"(f.x), "=f"(f.y) : "l"(p)); return f;
}
__device__ __forceinline__ uint32_t smem_u32(const void* p) {
    uint32_t a;
    asm("{ .reg .u64 t; cvta.to.shared.u64 t, %1; cvt.u32.u64 %0, t; }" : "=r"(a) : "l"(p));
    return a;
}
__device__ __forceinline__ void split2h(float f0, float f1, uint32_t& hi, uint32_t& lo) {
    __half2 h = __floats2half2_rn(f0, f1);
    float2 hf = __half22float2(h);
    __half2 l = __floats2half2_rn(f0 - hf.x, f1 - hf.y);
    hi = *(uint32_t*)&h;
    lo = *(uint32_t*)&l;
}
__device__ __forceinline__ uint32_t cvt2h(float f0, float f1) {
    __half2 h = __floats2half2_rn(f0, f1);
    return *(uint32_t*)&h;
}
__device__ __forceinline__ uint32_t swz(uint32_t off) { return off ^ ((off >> 3) & 0x70); }

__device__ __forceinline__ void ldsm4(uint32_t& r0, uint32_t& r1, uint32_t& r2, uint32_t& r3, uint32_t a) {
    asm volatile("ldmatrix.sync.aligned.m8n8.x4.shared.b16 {%0,%1,%2,%3}, [%4];"
                 : "=r"(r0), "=r"(r1), "=r"(r2), "=r"(r3) : "r"(a));
}
__device__ __forceinline__ void ldsm4t(uint32_t& r0, uint32_t& r1, uint32_t& r2, uint32_t& r3, uint32_t a) {
    asm volatile("ldmatrix.sync.aligned.m8n8.x4.trans.shared.b16 {%0,%1,%2,%3}, [%4];"
                 : "=r"(r0), "=r"(r1), "=r"(r2), "=r"(r3) : "r"(a));
}
__device__ __forceinline__ void mma16816(float* d, const uint32_t* a, uint32_t b0, uint32_t b1) {
    asm volatile("mma.sync.aligned.m16n8k16.row.col.f32.f16.f16.f32 "
                 "{%0,%1,%2,%3}, {%4,%5,%6,%7}, {%8,%9}, {%0,%1,%2,%3};"
                 : "+f"(d[0]), "+f"(d[1]), "+f"(d[2]), "+f"(d[3])
                 : "r"(a[0]), "r"(a[1]), "r"(a[2]), "r"(a[3]), "r"(b0), "r"(b1));
}

__global__ void __launch_bounds__(NT, 1)
fml_kernel(const float* __restrict__ gq, const float* __restrict__ gk,
           const float* __restrict__ gv, const float* __restrict__ gkcg,
           const float* __restrict__ gvcg, float* __restrict__ gout)
{
    extern __shared__ float sm[];
    char* smc = (char*)sm;
    const int b   = blockIdx.x;
    const int tid = threadIdx.x;
    const int wid = tid >> 5, lane = tid & 31;
    const float scale = 0.088388347648318447f;
    const uint32_t smb = smem_u32(sm);

    // ldmatrix lane geometry
    const int grp = lane >> 3, li = lane & 7;
    const int arow = (grp & 1) * 8 + li;
    const int akc  = (grp >> 1) * 8;
    const int asrow = (grp >> 1) * 8 + li;
    const int ascol = (grp & 1) * 8;
    const int bsrow = (grp & 1) * 8 + li;
    const int bscol = (grp >> 1) * 8;
    const int brow = (grp >> 1) * 8 + li;
    const int bkc  = (grp & 1) * 8;

    // ---- load qT, stage Q fp16, load cg tensors ----
    const float* qb = gq + (size_t)b * Qn * Dn;
    for (int i = tid; i < Qn * Dn; i += NT) {
        int qq = i >> 7, d = i & 127;
        sm[OFF_QT + d * 16 + qq] = qb[i];
    }
    if (tid < 256) {
        int q = tid >> 4, dblk = tid & 15;
        const float* src = qb + q * Dn + dblk * 8;
        float4 f0 = *(const float4*)src;
        float4 f1 = *(const float4*)(src + 4);
        uint4 qh, ql;
        uint32_t h, l;
        split2h(f0.x, f0.y, h, l); qh.x = h; ql.x = l;
        split2h(f0.z, f0.w, h, l); qh.y = h; ql.y = l;
        split2h(f1.x, f1.y, h, l); qh.z = h; ql.z = l;
        split2h(f1.z, f1.w, h, l); qh.w = h; ql.w = l;
        uint32_t off = (uint32_t)(q * TPITCH + dblk * 16);
        *(uint4*)(smc + OFF_QH * 4 + off) = qh;
        *(uint4*)(smc + OFF_QL * 4 + off) = ql;
    }
    const float* kcb = gkcg + (size_t)b * Mn * Dn;
    const float* vcb = gvcg + (size_t)b * Mn * Dn;
    for (int i = tid; i < Mn * Dn; i += NT) {
        int j = i >> 7, d = i & 127;
        sm[OFF_KCG + j * CGP + d] = kcb[i];
        sm[OFF_VCG + j * CGP + d] = vcb[i];
    }
    __syncthreads();

    // ---- cg scores / softmax / w_cg / out / kbar (exact SIMT) ----
    if (tid < Qn * Mn) {
        int qq = tid >> 3, j = tid & 7;
        float acc = 0.f;
        #pragma unroll 8
        for (int d = 0; d < Dn; ++d)
            acc = fmaf(sm[OFF_QT + d * 16 + qq], sm[OFF_KCG + j * CGP + d], acc);
        sm[OFF_PCG + qq * Mn + j] = acc * scale;
    }
    __syncthreads();
    if (tid < Qn) {
        float m = -1e30f;
        #pragma unroll
        for (int j = 0; j < Mn; ++j) m = fmaxf(m, sm[OFF_PCG + tid * Mn + j]);
        float ss = 0.f;
        #pragma unroll
        for (int j = 0; j < Mn; ++j) {
            float e = __expf(sm[OFF_PCG + tid * Mn + j] - m);
            sm[OFF_PCG + tid * Mn + j] = e; ss += e;
        }
        float inv = 1.f / ss;
        #pragma unroll
        for (int j = 0; j < Mn; ++j) sm[OFF_PCG + tid * Mn + j] *= inv;
    }
    __syncthreads();
    if (tid < Mn) {
        float a = 0.f;
        #pragma unroll
        for (int qq = 0; qq < Qn; ++qq) a += sm[OFF_PCG + qq * Mn + tid];
        sm[OFF_WCG + tid] = a;
    }
    if (tid < 256) {
        int qq = tid >> 4, dblk = tid & 15;
        ull o2[4], kb2[4];
        #pragma unroll
        for (int i = 0; i < 4; ++i) { o2[i] = 0ull; kb2[i] = 0ull; }
        #pragma unroll
        for (int j = 0; j < Mn; ++j) {
            ull pc2 = dup2(sm[OFF_PCG + qq * Mn + j]);
            ulonglong2 vA = *(const ulonglong2*)&sm[OFF_VCG + j * CGP + dblk * 8];
            ulonglong2 vB = *(const ulonglong2*)&sm[OFF_VCG + j * CGP + dblk * 8 + 4];
            ulonglong2 kA = *(const ulonglong2*)&sm[OFF_KCG + j * CGP + dblk * 8];
            ulonglong2 kB = *(const ulonglong2*)&sm[OFF_KCG + j * CGP + dblk * 8 + 4];
            o2[0]  = fma2(pc2, vA.x, o2[0]);  o2[1]  = fma2(pc2, vA.y, o2[1]);
            o2[2]  = fma2(pc2, vB.x, o2[2]);  o2[3]  = fma2(pc2, vB.y, o2[3]);
            kb2[0] = fma2(pc2, kA.x, kb2[0]); kb2[1] = fma2(pc2, kA.y, kb2[1]);
            kb2[2] = fma2(pc2, kB.x, kb2[2]); kb2[3] = fma2(pc2, kB.y, kb2[3]);
        }
        *(ulonglong2*)&sm[OFF_OCG  + qq * Dn + dblk * 8]     = make_ulonglong2(o2[0], o2[1]);
        *(ulonglong2*)&sm[OFF_OCG  + qq * Dn + dblk * 8 + 4] = make_ulonglong2(o2[2], o2[3]);
        *(ulonglong2*)&sm[OFF_KBCG + qq * Dn + dblk * 8]     = make_ulonglong2(kb2[0], kb2[1]);
        *(ulonglong2*)&sm[OFF_KBCG + qq * Dn + dblk * 8 + 4] = make_ulonglong2(kb2[2], kb2[3]);
    }

    // ---- dense scores via HMMA (pipelined K prefetch) ----
    const float* kbase = gk + (size_t)b * Sn * Dn;
    const float* vbase = gv + (size_t)b * Sn * Dn;
    const int r  = lane >> 2;
    const int cq = (lane & 3) * 2;
    const int ps  = tid >> 4;
    const int pdb = tid & 15;

    float4 sk[4];
    {
        const float* k0p = kbase + (size_t)ps * Dn + pdb * 8;
        const float* k1p = kbase + (size_t)(ps + 32) * Dn + pdb * 8;
        sk[0] = *(const float4*)k0p; sk[1] = *(const float4*)(k0p + 4);
        sk[2] = *(const float4*)k1p; sk[3] = *(const float4*)(k1p + 4);
    }
    for (int t = 0; t < NCHUNK; ++t) {
        __syncthreads();
        #pragma unroll
        for (int it = 0; it < 2; ++it) {
            int s = ps + it * 32;
            float4 k0 = sk[it * 2], k1 = sk[it * 2 + 1];
            uint4 kh, kl;
            uint32_t h, l;
            split2h(k0.x, k0.y, h, l); kh.x = h; kl.x = l;
            split2h(k0.z, k0.w, h, l); kh.y = h; kl.y = l;
            split2h(k1.x, k1.y, h, l); kh.z = h; kl.z = l;
            split2h(k1.z, k1.w, h, l); kh.w = h; kl.w = l;
            uint32_t off = (uint32_t)(s * TPITCH + pdb * 16);
            *(uint4*)(smc + OFF_SKH * 4 + off) = kh;
            *(uint4*)(smc + OFF_SKL * 4 + off) = kl;
        }
        if (t + 1 < NCHUNK) {
            const float* k0p = kbase + (size_t)((t + 1) * TILE + ps) * Dn + pdb * 8;
            const float* k1p = kbase + (size_t)((t + 1) * TILE + ps + 32) * Dn + pdb * 8;
            sk[0] = *(const float4*)k0p; sk[1] = *(const float4*)(k0p + 4);
            sk[2] = *(const float4*)k1p; sk[3] = *(const float4*)(k1p + 4);
        }
        __syncthreads();
        if (wid < 8) {
            int mw = wid & 3;
            int qj = wid >> 2;
            float accS[4] = {0.f, 0.f, 0.f, 0.f};
            #pragma unroll
            for (int k = 0; k < 8; ++k) {
                uint32_t ah[4], al[4], qh[4], qlr[4];
                uint32_t aoff = (uint32_t)((mw * 16 + arow) * TPITCH + (k * 16 + akc) * 2);
                ldsm4(ah[0], ah[1], ah[2], ah[3], smb + OFF_SKH * 4 + aoff);
                ldsm4(al[0], al[1], al[2], al[3], smb + OFF_SKL * 4 + aoff);
                uint32_t boff = (uint32_t)(brow * TPITCH + (k * 16 + bkc) * 2);
                ldsm4(qh[0], qh[1], qh[2], qh[3], smb + OFF_QH * 4 + boff);
                ldsm4(qlr[0], qlr[1], qlr[2], qlr[3], smb + OFF_QL * 4 + boff);
                int bs = qj * 2;
                mma16816(accS, ah, qh[bs], qh[bs + 1]);
                mma16816(accS, ah, qlr[bs], qlr[bs + 1]);
                mma16816(accS, al, qh[bs], qh[bs + 1]);
            }
            int sb = t * TILE + mw * 16;
            int q0 = qj * 8 + cq;
            sm[OFF_P + q0 * PPITCH + sb + r]           = accS[0] * scale;
            sm[OFF_P + (q0 + 1) * PPITCH + sb + r]     = accS[1] * scale;
            sm[OFF_P + q0 * PPITCH + sb + r + 8]       = accS[2] * scale;
            sm[OFF_P + (q0 + 1) * PPITCH + sb + r + 8] = accS[3] * scale;
        }
    }
    __syncthreads();

    // ---- softmax: one row per warp ----
    {
        float* row = &sm[OFF_P + wid * PPITCH];
        float m = -1e30f;
        #pragma unroll
        for (int i = 0; i < 16; ++i) m = fmaxf(m, row[lane + 32 * i]);
        #pragma unroll
        for (int o = 16; o > 0; o >>= 1) m = fmaxf(m, __shfl_xor_sync(0xffffffffu, m, o));
        float ss = 0.f;
        float ev[16];
        #pragma unroll
        for (int i = 0; i < 16; ++i) { ev[i] = __expf(row[lane + 32 * i] - m); ss += ev[i]; }
        #pragma unroll
        for (int o = 16; o > 0; o >>= 1) ss += __shfl_xor_sync(0xffffffffu, ss, o);
        float inv = 1.f / ss;
        #pragma unroll
        for (int i = 0; i < 16; ++i) row[lane + 32 * i] = ev[i] * inv;
    }
    __syncthreads();
    {
        int s = tid;
        float a = 0.f;
        #pragma unroll
        for (int qq = 0; qq < Qn; ++qq) a += sm[OFF_P + qq * PPITCH + s];
        sm[OFF_W + s] = a;
    }

    // ---- main tensor-core pass (pipelined K/V prefetch) ----
    const int mw   = wid & 7;
    const int m0   = mw * 16;
    const int nj   = wid >> 3;

    float accJ[8][4];
    float accO[2][4];
    #pragma unroll
    for (int nt = 0; nt < 8; ++nt)
        #pragma unroll
        for (int e = 0; e < 4; ++e) accJ[nt][e] = 0.f;
    #pragma unroll
    for (int nt = 0; nt < 2; ++nt)
        #pragma unroll
        for (int e = 0; e < 4; ++e) accO[nt][e] = 0.f;

    float4 pk[4], pv[4];
    {
        const float* k0p = kbase + (size_t)ps * Dn + pdb * 8;
        const float* k1p = kbase + (size_t)(ps + 32) * Dn + pdb * 8;
        const float* v0p = vbase + (size_t)ps * Dn + pdb * 8;
        const float* v1p = vbase + (size_t)(ps + 32) * Dn + pdb * 8;
        pk[0] = *(const float4*)k0p; pk[1] = *(const float4*)(k0p + 4);
        pk[2] = *(const float4*)k1p; pk[3] = *(const float4*)(k1p + 4);
        pv[0] = *(const float4*)v0p; pv[1] = *(const float4*)(v0p + 4);
        pv[2] = *(const float4*)v1p; pv[3] = *(const float4*)(v1p + 4);
    }

    for (int c = 0; c < NCHUNK; ++c) {
        const int s0 = c * TILE;
        __syncthreads();
        #pragma unroll
        for (int it = 0; it < 2; ++it) {
            int s = ps + it * 32;
            float4 k0 = pk[it * 2], k1 = pk[it * 2 + 1];
            float4 v0 = pv[it * 2], v1 = pv[it * 2 + 1];
            float ws = sm[OFF_W + s0 + s];
            uint32_t off = (uint32_t)(s * TPITCH + pdb * 16);
            *(uint4*)(smc + OFF_KH * 4 + off) =
                make_uint4(cvt2h(k0.x, k0.y), cvt2h(k0.z, k0.w),
                           cvt2h(k1.x, k1.y), cvt2h(k1.z, k1.w));
            *(uint4*)(smc + OFF_WKH * 4 + off) =
                make_uint4(cvt2h(k0.x * ws, k0.y * ws), cvt2h(k0.z * ws, k0.w * ws),
                           cvt2h(k1.x * ws, k1.y * ws), cvt2h(k1.z * ws, k1.w * ws));
            uint4 vh, vl;
            uint32_t h, l;
            split2h(v0.x, v0.y, h, l); vh.x = h; vl.x = l;
            split2h(v0.z, v0.w, h, l); vh.y = h; vl.y = l;
            split2h(v1.x, v1.y, h, l); vh.z = h; vl.z = l;
            split2h(v1.z, v1.w, h, l); vh.w = h; vl.w = l;
            *(uint4*)(smc + OFF_VH * 4 + off) = vh;
            *(uint4*)(smc + OFF_VL * 4 + off) = vl;
        }
        {
            int qq = wid;
            float p0 = sm[OFF_P + qq * PPITCH + s0 + 2 * lane];
            float p1 = sm[OFF_P + qq * PPITCH + s0 + 2 * lane + 1];
            uint32_t sw = swz((uint32_t)(qq * 128 + lane * 4));
            uint32_t hi, lo;
            split2h(p0, p1, hi, lo);
            *(uint32_t*)(smc + OFF_PH * 4 + sw) = hi;
            *(uint32_t*)(smc + OFF_PL * 4 + sw) = lo;
        }
        if (c + 1 < NCHUNK) {
            const float* k0p = kbase + (size_t)((c + 1) * TILE + ps) * Dn + pdb * 8;
            const float* k1p = kbase + (size_t)((c + 1) * TILE + ps + 32) * Dn + pdb * 8;
            const float* v0p = vbase + (size_t)((c + 1) * TILE + ps) * Dn + pdb * 8;
            const float* v1p = vbase + (size_t)((c + 1) * TILE + ps + 32) * Dn + pdb * 8;
            pk[0] = *(const float4*)k0p; pk[1] = *(const float4*)(k0p + 4);
            pk[2] = *(const float4*)k1p; pk[3] = *(const float4*)(k1p + 4);
            pv[0] = *(const float4*)v0p; pv[1] = *(const float4*)(v0p + 4);
            pv[2] = *(const float4*)v1p; pv[3] = *(const float4*)(v1p + 4);
        }
        __syncthreads();

        #pragma unroll
        for (int k = 0; k < 4; ++k) {
            uint32_t vah[4];
            uint32_t aoff = (uint32_t)((k * 16 + asrow) * TPITCH + (m0 + ascol) * 2);
            ldsm4t(vah[0], vah[1], vah[2], vah[3], smb + OFF_VH * 4 + aoff);

            uint32_t ph[4];
            uint32_t pa = swz((uint32_t)(brow * 128 + (k * 16 + bkc) * 2));
            ldsm4(ph[0], ph[1], ph[2], ph[3], smb + OFF_PH * 4 + pa);

            if (nj == 0) {
                // out = V * p  (3-combo: Vh*Ph + Vh*Pl + Vl*Ph)
                uint32_t valo[4], pl[4];
                ldsm4t(valo[0], valo[1], valo[2], valo[3], smb + OFF_VL * 4 + aoff);
                ldsm4(pl[0], pl[1], pl[2], pl[3], smb + OFF_PL * 4 + pa);
                mma16816(accO[0], vah, ph[0], ph[1]);
                mma16816(accO[0], vah, pl[0], pl[1]);
                mma16816(accO[0], valo, ph[0], ph[1]);
                mma16816(accO[1], vah, ph[2], ph[3]);
                mma16816(accO[1], vah, pl[2], pl[3]);
                mma16816(accO[1], valo, ph[2], ph[3]);
            } else {
                // kbar = K * p  (1-combo: Kh*Ph)
                uint32_t kah[4];
                ldsm4t(kah[0], kah[1], kah[2], kah[3], smb + OFF_KH * 4 + aoff);
                mma16816(accO[0], kah, ph[0], ph[1]);
                mma16816(accO[1], kah, ph[2], ph[3]);
            }
            // J1 (1-combo: Vh*Wh)
            #pragma unroll
            for (int np = 0; np < 4; ++np) {
                uint32_t bh[4];
                uint32_t ba = (uint32_t)((k * 16 + bsrow) * TPITCH +
                                         (nj * 64 + np * 16 + bscol) * 2);
                ldsm4t(bh[0], bh[1], bh[2], bh[3], smb + OFF_WKH * 4 + ba);
                mma16816(accJ[np * 2], vah, bh[0], bh[1]);
                mma16816(accJ[np * 2 + 1], vah, bh[2], bh[3]);
            }
        }
    }
    __syncthreads();

    // ---- write out^T (nj==0) / kbar^T (nj==1) to smem [q][d] ----
    {
        int base = (nj == 0) ? OFF_OUT : OFF_KBAR;
        #pragma unroll
        for (int nt = 0; nt < 2; ++nt) {
            int qq = nt * 8 + cq;
            sm[base + qq * Dn + m0 + r]           = accO[nt][0];
            sm[base + (qq + 1) * Dn + m0 + r]     = accO[nt][1];
            sm[base + qq * Dn + m0 + r + 8]       = accO[nt][2];
            sm[base + (qq + 1) * Dn + m0 + r + 8] = accO[nt][3];
        }
    }
    __syncthreads();

    // ---- epilogue: J2 + cg jacobian + clip + cosine ----
    float o0a[16], o1a[16], c0a[16], c1a[16], vc0[8], vc1[8];
    #pragma unroll
    for (int q = 0; q < 16; ++q) {
        o0a[q] = sm[OFF_OUT + q * Dn + m0 + r];
        o1a[q] = sm[OFF_OUT + q * Dn + m0 + r + 8];
        c0a[q] = sm[OFF_OCG + q * Dn + m0 + r];
        c1a[q] = sm[OFF_OCG + q * Dn + m0 + r + 8];
    }
    #pragma unroll
    for (int j = 0; j < 8; ++j) {
        float wc = sm[OFF_WCG + j];
        vc0[j] = wc * sm[OFF_VCG + j * CGP + m0 + r];
        vc1[j] = wc * sm[OFF_VCG + j * CGP + m0 + r + 8];
    }

    float dd = 0.f, ccv = 0.f, dc = 0.f;
    #pragma unroll
    for (int nt = 0; nt < 8; ++nt) {
        ull jd0, jd1, jc0, jc1;
        asm("mov.b64 %0, {%1, %2};" : "=l"(jd0) : "f"(accJ[nt][0]), "f"(accJ[nt][1]));
        asm("mov.b64 %0, {%1, %2};" : "=l"(jd1) : "f"(accJ[nt][2]), "f"(accJ[nt][3]));
        jc0 = 0ull; jc1 = 0ull;
        int colb = nj * 64 + nt * 8 + cq;
        #pragma unroll
        for (int q = 0; q < 16; ++q) {
            ull kbp = *(const ull*)&sm[OFF_KBAR + q * Dn + colb];
            jd0 = fma2(dup2(-o0a[q]), kbp, jd0);
            jd1 = fma2(dup2(-o1a[q]), kbp, jd1);
        }
        #pragma unroll
        for (int j = 0; j < 8; ++j) {
            ull kcp = *(const ull*)&sm[OFF_KCG + j * CGP + colb];
            jc0 = fma2(dup2(vc0[j]), kcp, jc0);
            jc1 = fma2(dup2(vc1[j]), kcp, jc1);
        }
        #pragma unroll
        for (int q = 0; q < 16; ++q) {
            ull kbp = *(const ull*)&sm[OFF_KBCG + q * Dn + colb];
            jc0 = fma2(dup2(-c0a[q]), kbp, jc0);
            jc1 = fma2(dup2(-c1a[q]), kbp, jc1);
        }
        float2 d0 = unpack2(jd0), d1 = unpack2(jd1);
        float2 g0 = unpack2(jc0), g1 = unpack2(jc1);
        float jdv[4] = {d0.x, d0.y, d1.x, d1.y};
        float jcv[4] = {g0.x, g0.y, g1.x, g1.y};
        #pragma unroll
        for (int e = 0; e < 4; ++e) {
            float a = clip50(jdv[e] * scale);
            float g = clip50(jcv[e] * scale);
            dd  = fmaf(a, a, dd);
            ccv = fmaf(g, g, ccv);
            dc  = fmaf(a, g, dc);
        }
    }
    float cons = 0.f;
    #pragma unroll
    for (int i = 0; i < 4; ++i) {
        float dif = sm[OFF_OUT + tid * 4 + i] - sm[OFF_OCG + tid * 4 + i];
        cons = fmaf(dif, dif, cons);
    }

    #pragma unroll
    for (int o = 16; o > 0; o >>= 1) {
        dd   += __shfl_xor_sync(0xffffffffu, dd,   o);
        ccv  += __shfl_xor_sync(0xffffffffu, ccv,  o);
        dc   += __shfl_xor_sync(0xffffffffu, dc,   o);
        cons += __shfl_xor_sync(0xffffffffu, cons, o);
    }
    if (lane == 0) {
        sm[OFF_RED + wid * 4 + 0] = dd;
        sm[OFF_RED + wid * 4 + 1] = ccv;
        sm[OFF_RED + wid * 4 + 2] = dc;
        sm[OFF_RED + wid * 4 + 3] = cons;
    }
    __syncthreads();
    if (tid == 0) {
        float DD = 0.f, CC = 0.f, DC = 0.f, CO = 0.f;
        #pragma unroll
        for (int w8 = 0; w8 < 16; ++w8) {
            DD += sm[OFF_RED + w8 * 4 + 0];
            CC += sm[OFF_RED + w8 * 4 + 1];
            DC += sm[OFF_RED + w8 * 4 + 2];
            CO += sm[OFF_RED + w8 * 4 + 3];
        }
        float cosv = DC / (sqrtf(DD) * sqrtf(CC) + 1e-8f);
        g_losses[b] = (1.0f - cosv) + CO * (1.0f / (float)(Qn * Dn));
    }

    // ---- fused final reduction ----
    if (wid == 0) {
        unsigned int ticket = 0;
        if (lane == 0) {
            __threadfence();
            ticket = atomicInc(&g_count, Bn - 1);
        }
        ticket = __shfl_sync(0xffffffffu, ticket, 0);
        if (ticket == Bn - 1) {
            float a = 0.f;
            #pragma unroll
            for (int i = 0; i < 8; ++i) a += g_losses[lane * 8 + i];
            #pragma unroll
            for (int o = 16; o > 0; o >>= 1) a += __shfl_xor_sync(0xffffffffu, a, o);
            if (lane == 0) gout[0] = a * (1.0f / (float)Bn);
        }
    }
}

extern "C" void kernel_launch(void* const* d_in, const int* in_sizes, int n_in,
                              void* d_out, int out_size)
{
    const float* q   = (const float*)d_in[0];
    const float* k   = (const float*)d_in[1];
    const float* v   = (const float*)d_in[2];
    const float* kcg = (const float*)d_in[3];
    const float* vcg = (const float*)d_in[4];

    cudaFuncSetAttribute(fml_kernel, cudaFuncAttributeMaxDynamicSharedMemorySize,
                         SMEM_FLOATS * (int)sizeof(float));
    fml_kernel<<<Bn, NT, SMEM_FLOATS * sizeof(float)>>>(q, k, v, kcg, vcg, (float*)d_out);
}

// round 17
// speedup vs baseline: 1.2075x; 1.0477x over previous
#include <cuda_runtime.h>
#include <cuda_fp16.h>
#include <cstdint>

#define Bn 256
#define Qn 16
#define Sn 512
#define Mn 8
#define Dn 128
#define NT 512
#define TILE 64
#define NCHUNK 8
#define PPITCH 520
#define CGP 132
#define TPITCH 272

typedef unsigned long long ull;

// ---- shared memory layout (float offsets) ----
#define OFF_QT   0
#define OFF_P    2048
#define OFF_W    10368
#define OFF_OUT  10880
#define OFF_KBAR 12928
#define OFF_OCG  14976
#define OFF_KBCG 17024
#define OFF_KCG  19072
#define OFF_VCG  20128
#define OFF_PCG  21184
#define OFF_WCG  21312
#define OFF_RED  21320
#define OFF_VH   29696
#define OFF_VL   34048
#define OFF_WKH  42752
#define OFF_PH   47104
#define OFF_PL   47616
#define OFF_PPH  48128      // p' = p/w fp16 [16 q][64 s], 512 floats
#define SMEM_FLOATS 48640   // 194560 bytes
// scores-phase aliases (time-separated):
#define OFF_SKH  OFF_VH
#define OFF_QH   OFF_WKH
#define OFF_QL   (OFF_WKH + 1088)

__device__ float g_losses[Bn];
__device__ unsigned int g_count;

__device__ __forceinline__ float clip50(float x) {
    return fminf(fmaxf(x, -50.0f), 50.0f);
}
__device__ __forceinline__ ull dup2(float x) {
    ull r; asm("mov.b64 %0, {%1, %1};" : "=l"(r) : "f"(x)); return r;
}
__device__ __forceinline__ ull fma2(ull a, ull b, ull c) {
    ull d; asm("fma.rn.f32x2 %0, %1, %2, %3;" : "=l"(d) : "l"(a), "l"(b), "l"(c)); return d;
}
__device__ __forceinline__ float2 unpack2(ull p) {
    float2 f; asm("mov.b64 {%0, %1}, %2;" : "=f"(f.x), "=f"(f.y) : "l"(p)); return f;
}
__device__ __forceinline__ uint32_t smem_u32(const void* p) {
    uint32_t a;
    asm("{ .reg .u64 t; cvta.to.shared.u64 t, %1; cvt.u32.u64 %0, t; }" : "=r"(a) : "l"(p));
    return a;
}
__device__ __forceinline__ void split2h(float f0, float f1, uint32_t& hi, uint32_t& lo) {
    __half2 h = __floats2half2_rn(f0, f1);
    float2 hf = __half22float2(h);
    __half2 l = __floats2half2_rn(f0 - hf.x, f1 - hf.y);
    hi = *(uint32_t*)&h;
    lo = *(uint32_t*)&l;
}
__device__ __forceinline__ uint32_t cvt2h(float f0, float f1) {
    __half2 h = __floats2half2_rn(f0, f1);
    return *(uint32_t*)&h;
}
__device__ __forceinline__ uint32_t swz(uint32_t off) { return off ^ ((off >> 3) & 0x70); }

__device__ __forceinline__ void ldsm4(uint32_t& r0, uint32_t& r1, uint32_t& r2, uint32_t& r3, uint32_t a) {
    asm volatile("ldmatrix.sync.aligned.m8n8.x4.shared.b16 {%0,%1,%2,%3}, [%4];"
                 : "=r"(r0), "=r"(r1), "=r"(r2), "=r"(r3) : "r"(a));
}
__device__ __forceinline__ void ldsm4t(uint32_t& r0, uint32_t& r1, uint32_t& r2, uint32_t& r3, uint32_t a) {
    asm volatile("ldmatrix.sync.aligned.m8n8.x4.trans.shared.b16 {%0,%1,%2,%3}, [%4];"
                 : "=r"(r0), "=r"(r1), "=r"(r2), "=r"(r3) : "r"(a));
}
__device__ __forceinline__ void mma16816(float* d, const uint32_t* a, uint32_t b0, uint32_t b1) {
    asm volatile("mma.sync.aligned.m16n8k16.row.col.f32.f16.f16.f32 "
                 "{%0,%1,%2,%3}, {%4,%5,%6,%7}, {%8,%9}, {%0,%1,%2,%3};"
                 : "+f"(d[0]), "+f"(d[1]), "+f"(d[2]), "+f"(d[3])
                 : "r"(a[0]), "r"(a[1]), "r"(a[2]), "r"(a[3]), "r"(b0), "r"(b1));
}

__global__ void __launch_bounds__(NT, 1)
fml_kernel(const float* __restrict__ gq, const float* __restrict__ gk,
           const float* __restrict__ gv, const float* __restrict__ gkcg,
           const float* __restrict__ gvcg, float* __restrict__ gout)
{
    extern __shared__ float sm[];
    char* smc = (char*)sm;
    const int b   = blockIdx.x;
    const int tid = threadIdx.x;
    const int wid = tid >> 5, lane = tid & 31;
    const float scale = 0.088388347648318447f;
    const uint32_t smb = smem_u32(sm);

    // ldmatrix lane geometry
    const int grp = lane >> 3, li = lane & 7;
    const int arow = (grp & 1) * 8 + li;
    const int akc  = (grp >> 1) * 8;
    const int asrow = (grp >> 1) * 8 + li;
    const int ascol = (grp & 1) * 8;
    const int bsrow = (grp & 1) * 8 + li;
    const int bscol = (grp >> 1) * 8;
    const int brow = (grp >> 1) * 8 + li;
    const int bkc  = (grp & 1) * 8;

    // ---- load qT, stage Q fp16, load cg tensors ----
    const float* qb = gq + (size_t)b * Qn * Dn;
    for (int i = tid; i < Qn * Dn; i += NT) {
        int qq = i >> 7, d = i & 127;
        sm[OFF_QT + d * 16 + qq] = qb[i];
    }
    if (tid < 256) {
        int q = tid >> 4, dblk = tid & 15;
        const float* src = qb + q * Dn + dblk * 8;
        float4 f0 = *(const float4*)src;
        float4 f1 = *(const float4*)(src + 4);
        uint4 qh, ql;
        uint32_t h, l;
        split2h(f0.x, f0.y, h, l); qh.x = h; ql.x = l;
        split2h(f0.z, f0.w, h, l); qh.y = h; ql.y = l;
        split2h(f1.x, f1.y, h, l); qh.z = h; ql.z = l;
        split2h(f1.z, f1.w, h, l); qh.w = h; ql.w = l;
        uint32_t off = (uint32_t)(q * TPITCH + dblk * 16);
        *(uint4*)(smc + OFF_QH * 4 + off) = qh;
        *(uint4*)(smc + OFF_QL * 4 + off) = ql;
    }
    const float* kcb = gkcg + (size_t)b * Mn * Dn;
    const float* vcb = gvcg + (size_t)b * Mn * Dn;
    for (int i = tid; i < Mn * Dn; i += NT) {
        int j = i >> 7, d = i & 127;
        sm[OFF_KCG + j * CGP + d] = kcb[i];
        sm[OFF_VCG + j * CGP + d] = vcb[i];
    }
    __syncthreads();

    // ---- cg scores / softmax / w_cg / out / kbar (exact SIMT) ----
    if (tid < Qn * Mn) {
        int qq = tid >> 3, j = tid & 7;
        float acc = 0.f;
        #pragma unroll 8
        for (int d = 0; d < Dn; ++d)
            acc = fmaf(sm[OFF_QT + d * 16 + qq], sm[OFF_KCG + j * CGP + d], acc);
        sm[OFF_PCG + qq * Mn + j] = acc * scale;
    }
    __syncthreads();
    if (tid < Qn) {
        float m = -1e30f;
        #pragma unroll
        for (int j = 0; j < Mn; ++j) m = fmaxf(m, sm[OFF_PCG + tid * Mn + j]);
        float ss = 0.f;
        #pragma unroll
        for (int j = 0; j < Mn; ++j) {
            float e = __expf(sm[OFF_PCG + tid * Mn + j] - m);
            sm[OFF_PCG + tid * Mn + j] = e; ss += e;
        }
        float inv = 1.f / ss;
        #pragma unroll
        for (int j = 0; j < Mn; ++j) sm[OFF_PCG + tid * Mn + j] *= inv;
    }
    __syncthreads();
    if (tid < Mn) {
        float a = 0.f;
        #pragma unroll
        for (int qq = 0; qq < Qn; ++qq) a += sm[OFF_PCG + qq * Mn + tid];
        sm[OFF_WCG + tid] = a;
    }
    if (tid < 256) {
        int qq = tid >> 4, dblk = tid & 15;
        ull o2[4], kb2[4];
        #pragma unroll
        for (int i = 0; i < 4; ++i) { o2[i] = 0ull; kb2[i] = 0ull; }
        #pragma unroll
        for (int j = 0; j < Mn; ++j) {
            ull pc2 = dup2(sm[OFF_PCG + qq * Mn + j]);
            ulonglong2 vA = *(const ulonglong2*)&sm[OFF_VCG + j * CGP + dblk * 8];
            ulonglong2 vB = *(const ulonglong2*)&sm[OFF_VCG + j * CGP + dblk * 8 + 4];
            ulonglong2 kA = *(const ulonglong2*)&sm[OFF_KCG + j * CGP + dblk * 8];
            ulonglong2 kB = *(const ulonglong2*)&sm[OFF_KCG + j * CGP + dblk * 8 + 4];
            o2[0]  = fma2(pc2, vA.x, o2[0]);  o2[1]  = fma2(pc2, vA.y, o2[1]);
            o2[2]  = fma2(pc2, vB.x, o2[2]);  o2[3]  = fma2(pc2, vB.y, o2[3]);
            kb2[0] = fma2(pc2, kA.x, kb2[0]); kb2[1] = fma2(pc2, kA.y, kb2[1]);
            kb2[2] = fma2(pc2, kB.x, kb2[2]); kb2[3] = fma2(pc2, kB.y, kb2[3]);
        }
        *(ulonglong2*)&sm[OFF_OCG  + qq * Dn + dblk * 8]     = make_ulonglong2(o2[0], o2[1]);
        *(ulonglong2*)&sm[OFF_OCG  + qq * Dn + dblk * 8 + 4] = make_ulonglong2(o2[2], o2[3]);
        *(ulonglong2*)&sm[OFF_KBCG + qq * Dn + dblk * 8]     = make_ulonglong2(kb2[0], kb2[1]);
        *(ulonglong2*)&sm[OFF_KBCG + qq * Dn + dblk * 8 + 4] = make_ulonglong2(kb2[2], kb2[3]);
    }

    // ---- dense scores via HMMA (2-combo: Kh*Qh + Kh*Ql) ----
    const float* kbase = gk + (size_t)b * Sn * Dn;
    const float* vbase = gv + (size_t)b * Sn * Dn;
    const int r  = lane >> 2;
    const int cq = (lane & 3) * 2;
    const int ps  = tid >> 4;
    const int pdb = tid & 15;

    float4 sk[4];
    {
        const float* k0p = kbase + (size_t)ps * Dn + pdb * 8;
        const float* k1p = kbase + (size_t)(ps + 32) * Dn + pdb * 8;
        sk[0] = *(const float4*)k0p; sk[1] = *(const float4*)(k0p + 4);
        sk[2] = *(const float4*)k1p; sk[3] = *(const float4*)(k1p + 4);
    }
    for (int t = 0; t < NCHUNK; ++t) {
        __syncthreads();
        #pragma unroll
        for (int it = 0; it < 2; ++it) {
            int s = ps + it * 32;
            float4 k0 = sk[it * 2], k1 = sk[it * 2 + 1];
            uint32_t off = (uint32_t)(s * TPITCH + pdb * 16);
            *(uint4*)(smc + OFF_SKH * 4 + off) =
                make_uint4(cvt2h(k0.x, k0.y), cvt2h(k0.z, k0.w),
                           cvt2h(k1.x, k1.y), cvt2h(k1.z, k1.w));
        }
        if (t + 1 < NCHUNK) {
            const float* k0p = kbase + (size_t)((t + 1) * TILE + ps) * Dn + pdb * 8;
            const float* k1p = kbase + (size_t)((t + 1) * TILE + ps + 32) * Dn + pdb * 8;
            sk[0] = *(const float4*)k0p; sk[1] = *(const float4*)(k0p + 4);
            sk[2] = *(const float4*)k1p; sk[3] = *(const float4*)(k1p + 4);
        }
        __syncthreads();
        if (wid < 8) {
            int mw = wid & 3;
            int qj = wid >> 2;
            float accS[4] = {0.f, 0.f, 0.f, 0.f};
            #pragma unroll
            for (int k = 0; k < 8; ++k) {
                uint32_t ah[4], qh[4], qlr[4];
                uint32_t aoff = (uint32_t)((mw * 16 + arow) * TPITCH + (k * 16 + akc) * 2);
                ldsm4(ah[0], ah[1], ah[2], ah[3], smb + OFF_SKH * 4 + aoff);
                uint32_t boff = (uint32_t)(brow * TPITCH + (k * 16 + bkc) * 2);
                ldsm4(qh[0], qh[1], qh[2], qh[3], smb + OFF_QH * 4 + boff);
                ldsm4(qlr[0], qlr[1], qlr[2], qlr[3], smb + OFF_QL * 4 + boff);
                int bs = qj * 2;
                mma16816(accS, ah, qh[bs], qh[bs + 1]);
                mma16816(accS, ah, qlr[bs], qlr[bs + 1]);
            }
            int sb = t * TILE + mw * 16;
            int q0 = qj * 8 + cq;
            sm[OFF_P + q0 * PPITCH + sb + r]           = accS[0] * scale;
            sm[OFF_P + (q0 + 1) * PPITCH + sb + r]     = accS[1] * scale;
            sm[OFF_P + q0 * PPITCH + sb + r + 8]       = accS[2] * scale;
            sm[OFF_P + (q0 + 1) * PPITCH + sb + r + 8] = accS[3] * scale;
        }
    }
    __syncthreads();

    // ---- softmax: one row per warp ----
    {
        float* row = &sm[OFF_P + wid * PPITCH];
        float m = -1e30f;
        #pragma unroll
        for (int i = 0; i < 16; ++i) m = fmaxf(m, row[lane + 32 * i]);
        #pragma unroll
        for (int o = 16; o > 0; o >>= 1) m = fmaxf(m, __shfl_xor_sync(0xffffffffu, m, o));
        float ss = 0.f;
        float ev[16];
        #pragma unroll
        for (int i = 0; i < 16; ++i) { ev[i] = __expf(row[lane + 32 * i] - m); ss += ev[i]; }
        #pragma unroll
        for (int o = 16; o > 0; o >>= 1) ss += __shfl_xor_sync(0xffffffffu, ss, o);
        float inv = 1.f / ss;
        #pragma unroll
        for (int i = 0; i < 16; ++i) row[lane + 32 * i] = ev[i] * inv;
    }
    __syncthreads();
    {
        int s = tid;
        float a = 0.f;
        #pragma unroll
        for (int qq = 0; qq < Qn; ++qq) a += sm[OFF_P + qq * PPITCH + s];
        sm[OFF_W + s] = a;
    }

    // ---- main tensor-core pass (pipelined K/V prefetch) ----
    const int mw   = wid & 7;
    const int m0   = mw * 16;
    const int nj   = wid >> 3;

    float accJ[8][4];
    float accO[2][4];
    #pragma unroll
    for (int nt = 0; nt < 8; ++nt)
        #pragma unroll
        for (int e = 0; e < 4; ++e) accJ[nt][e] = 0.f;
    #pragma unroll
    for (int nt = 0; nt < 2; ++nt)
        #pragma unroll
        for (int e = 0; e < 4; ++e) accO[nt][e] = 0.f;

    float4 pk[4], pv[4];
    {
        const float* k0p = kbase + (size_t)ps * Dn + pdb * 8;
        const float* k1p = kbase + (size_t)(ps + 32) * Dn + pdb * 8;
        const float* v0p = vbase + (size_t)ps * Dn + pdb * 8;
        const float* v1p = vbase + (size_t)(ps + 32) * Dn + pdb * 8;
        pk[0] = *(const float4*)k0p; pk[1] = *(const float4*)(k0p + 4);
        pk[2] = *(const float4*)k1p; pk[3] = *(const float4*)(k1p + 4);
        pv[0] = *(const float4*)v0p; pv[1] = *(const float4*)(v0p + 4);
        pv[2] = *(const float4*)v1p; pv[3] = *(const float4*)(v1p + 4);
    }

    for (int c = 0; c < NCHUNK; ++c) {
        const int s0 = c * TILE;
        __syncthreads();
        #pragma unroll
        for (int it = 0; it < 2; ++it) {
            int s = ps + it * 32;
            float4 k0 = pk[it * 2], k1 = pk[it * 2 + 1];
            float4 v0 = pv[it * 2], v1 = pv[it * 2 + 1];
            float ws = sm[OFF_W + s0 + s];
            uint32_t off = (uint32_t)(s * TPITCH + pdb * 16);
            *(uint4*)(smc + OFF_WKH * 4 + off) =
                make_uint4(cvt2h(k0.x * ws, k0.y * ws), cvt2h(k0.z * ws, k0.w * ws),
                           cvt2h(k1.x * ws, k1.y * ws), cvt2h(k1.z * ws, k1.w * ws));
            uint4 vh, vl;
            uint32_t h, l;
            split2h(v0.x, v0.y, h, l); vh.x = h; vl.x = l;
            split2h(v0.z, v0.w, h, l); vh.y = h; vl.y = l;
            split2h(v1.x, v1.y, h, l); vh.z = h; vl.z = l;
            split2h(v1.z, v1.w, h, l); vh.w = h; vl.w = l;
            *(uint4*)(smc + OFF_VH * 4 + off) = vh;
            *(uint4*)(smc + OFF_VL * 4 + off) = vl;
        }
        {
            int qq = wid;
            float p0 = sm[OFF_P + qq * PPITCH + s0 + 2 * lane];
            float p1 = sm[OFF_P + qq * PPITCH + s0 + 2 * lane + 1];
            float w0 = sm[OFF_W + s0 + 2 * lane];
            float w1 = sm[OFF_W + s0 + 2 * lane + 1];
            float pp0 = (w0 > 0.f) ? __fdividef(p0, w0) : 0.f;
            float pp1 = (w1 > 0.f) ? __fdividef(p1, w1) : 0.f;
            uint32_t sw = swz((uint32_t)(qq * 128 + lane * 4));
            uint32_t hi, lo;
            split2h(p0, p1, hi, lo);
            *(uint32_t*)(smc + OFF_PH * 4 + sw) = hi;
            *(uint32_t*)(smc + OFF_PL * 4 + sw) = lo;
            *(uint32_t*)(smc + OFF_PPH * 4 + sw) = cvt2h(pp0, pp1);
        }
        if (c + 1 < NCHUNK) {
            const float* k0p = kbase + (size_t)((c + 1) * TILE + ps) * Dn + pdb * 8;
            const float* k1p = kbase + (size_t)((c + 1) * TILE + ps + 32) * Dn + pdb * 8;
            const float* v0p = vbase + (size_t)((c + 1) * TILE + ps) * Dn + pdb * 8;
            const float* v1p = vbase + (size_t)((c + 1) * TILE + ps + 32) * Dn + pdb * 8;
            pk[0] = *(const float4*)k0p; pk[1] = *(const float4*)(k0p + 4);
            pk[2] = *(const float4*)k1p; pk[3] = *(const float4*)(k1p + 4);
            pv[0] = *(const float4*)v0p; pv[1] = *(const float4*)(v0p + 4);
            pv[2] = *(const float4*)v1p; pv[3] = *(const float4*)(v1p + 4);
        }
        __syncthreads();

        #pragma unroll
        for (int k = 0; k < 4; ++k) {
            uint32_t vah[4];
            uint32_t aoff = (uint32_t)((k * 16 + asrow) * TPITCH + (m0 + ascol) * 2);
            ldsm4t(vah[0], vah[1], vah[2], vah[3], smb + OFF_VH * 4 + aoff);

            if (nj == 0) {
                // out = V * p  (3-combo)
                uint32_t valo[4], ph[4], pl[4];
                uint32_t pa = swz((uint32_t)(brow * 128 + (k * 16 + bkc) * 2));
                ldsm4(ph[0], ph[1], ph[2], ph[3], smb + OFF_PH * 4 + pa);
                ldsm4(pl[0], pl[1], pl[2], pl[3], smb + OFF_PL * 4 + pa);
                ldsm4t(valo[0], valo[1], valo[2], valo[3], smb + OFF_VL * 4 + aoff);
                mma16816(accO[0], vah, ph[0], ph[1]);
                mma16816(accO[0], vah, pl[0], pl[1]);
                mma16816(accO[0], valo, ph[0], ph[1]);
                mma16816(accO[1], vah, ph[2], ph[3]);
                mma16816(accO[1], vah, pl[2], pl[3]);
                mma16816(accO[1], valo, ph[2], ph[3]);
            } else {
                // kbar = (wK) * p'  (1-combo: WKh * PPh)
                uint32_t wkh[4], pph[4];
                uint32_t pa = swz((uint32_t)(brow * 128 + (k * 16 + bkc) * 2));
                ldsm4t(wkh[0], wkh[1], wkh[2], wkh[3], smb + OFF_WKH * 4 + aoff);
                ldsm4(pph[0], pph[1], pph[2], pph[3], smb + OFF_PPH * 4 + pa);
                mma16816(accO[0], wkh, pph[0], pph[1]);
                mma16816(accO[1], wkh, pph[2], pph[3]);
            }
            // J1 (1-combo: Vh*Wh)
            #pragma unroll
            for (int np = 0; np < 4; ++np) {
                uint32_t bh[4];
                uint32_t ba = (uint32_t)((k * 16 + bsrow) * TPITCH +
                                         (nj * 64 + np * 16 + bscol) * 2);
                ldsm4t(bh[0], bh[1], bh[2], bh[3], smb + OFF_WKH * 4 + ba);
                mma16816(accJ[np * 2], vah, bh[0], bh[1]);
                mma16816(accJ[np * 2 + 1], vah, bh[2], bh[3]);
            }
        }
    }
    __syncthreads();

    // ---- write out^T (nj==0) / kbar^T (nj==1) to smem [q][d] ----
    {
        int base = (nj == 0) ? OFF_OUT : OFF_KBAR;
        #pragma unroll
        for (int nt = 0; nt < 2; ++nt) {
            int qq = nt * 8 + cq;
            sm[base + qq * Dn + m0 + r]           = accO[nt][0];
            sm[base + (qq + 1) * Dn + m0 + r]     = accO[nt][1];
            sm[base + qq * Dn + m0 + r + 8]       = accO[nt][2];
            sm[base + (qq + 1) * Dn + m0 + r + 8] = accO[nt][3];
        }
    }
    __syncthreads();

    // ---- epilogue: J2 + cg jacobian + clip + cosine ----
    float o0a[16], o1a[16], c0a[16], c1a[16], vc0[8], vc1[8];
    #pragma unroll
    for (int q = 0; q < 16; ++q) {
        o0a[q] = sm[OFF_OUT + q * Dn + m0 + r];
        o1a[q] = sm[OFF_OUT + q * Dn + m0 + r + 8];
        c0a[q] = sm[OFF_OCG + q * Dn + m0 + r];
        c1a[q] = sm[OFF_OCG + q * Dn + m0 + r + 8];
    }
    #pragma unroll
    for (int j = 0; j < 8; ++j) {
        float wc = sm[OFF_WCG + j];
        vc0[j] = wc * sm[OFF_VCG + j * CGP + m0 + r];
        vc1[j] = wc * sm[OFF_VCG + j * CGP + m0 + r + 8];
    }

    float dd = 0.f, ccv = 0.f, dc = 0.f;
    #pragma unroll
    for (int nt = 0; nt < 8; ++nt) {
        ull jd0, jd1, jc0, jc1;
        asm("mov.b64 %0, {%1, %2};" : "=l"(jd0) : "f"(accJ[nt][0]), "f"(accJ[nt][1]));
        asm("mov.b64 %0, {%1, %2};" : "=l"(jd1) : "f"(accJ[nt][2]), "f"(accJ[nt][3]));
        jc0 = 0ull; jc1 = 0ull;
        int colb = nj * 64 + nt * 8 + cq;
        #pragma unroll
        for (int q = 0; q < 16; ++q) {
            ull kbp = *(const ull*)&sm[OFF_KBAR + q * Dn + colb];
            jd0 = fma2(dup2(-o0a[q]), kbp, jd0);
            jd1 = fma2(dup2(-o1a[q]), kbp, jd1);
        }
        #pragma unroll
        for (int j = 0; j < 8; ++j) {
            ull kcp = *(const ull*)&sm[OFF_KCG + j * CGP + colb];
            jc0 = fma2(dup2(vc0[j]), kcp, jc0);
            jc1 = fma2(dup2(vc1[j]), kcp, jc1);
        }
        #pragma unroll
        for (int q = 0; q < 16; ++q) {
            ull kbp = *(const ull*)&sm[OFF_KBCG + q * Dn + colb];
            jc0 = fma2(dup2(-c0a[q]), kbp, jc0);
            jc1 = fma2(dup2(-c1a[q]), kbp, jc1);
        }
        float2 d0 = unpack2(jd0), d1 = unpack2(jd1);
        float2 g0 = unpack2(jc0), g1 = unpack2(jc1);
        float jdv[4] = {d0.x, d0.y, d1.x, d1.y};
        float jcv[4] = {g0.x, g0.y, g1.x, g1.y};
        #pragma unroll
        for (int e = 0; e < 4; ++e) {
            float a = clip50(jdv[e] * scale);
            float g = clip50(jcv[e] * scale);
            dd  = fmaf(a, a, dd);
            ccv = fmaf(g, g, ccv);
            dc  = fmaf(a, g, dc);
        }
    }
    float cons = 0.f;
    #pragma unroll
    for (int i = 0; i < 4; ++i) {
        float dif = sm[OFF_OUT + tid * 4 + i] - sm[OFF_OCG + tid * 4 + i];
        cons = fmaf(dif, dif, cons);
    }

    #pragma unroll
    for (int o = 16; o > 0; o >>= 1) {
        dd   += __shfl_xor_sync(0xffffffffu, dd,   o);
        ccv  += __shfl_xor_sync(0xffffffffu, ccv,  o);
        dc   += __shfl_xor_sync(0xffffffffu, dc,   o);
        cons += __shfl_xor_sync(0xffffffffu, cons, o);
    }
    if (lane == 0) {
        sm[OFF_RED + wid * 4 + 0] = dd;
        sm[OFF_RED + wid * 4 + 1] = ccv;
        sm[OFF_RED + wid * 4 + 2] = dc;
        sm[OFF_RED + wid * 4 + 3] = cons;
    }
    __syncthreads();
    if (tid == 0) {
        float DD = 0.f, CC = 0.f, DC = 0.f, CO = 0.f;
        #pragma unroll
        for (int w8 = 0; w8 < 16; ++w8) {
            DD += sm[OFF_RED + w8 * 4 + 0];
            CC += sm[OFF_RED + w8 * 4 + 1];
            DC += sm[OFF_RED + w8 * 4 + 2];
            CO += sm[OFF_RED + w8 * 4 + 3];
        }
        float cosv = DC / (sqrtf(DD) * sqrtf(CC) + 1e-8f);
        g_losses[b] = (1.0f - cosv) + CO * (1.0f / (float)(Qn * Dn));
    }

    // ---- fused final reduction ----
    if (wid == 0) {
        unsigned int ticket = 0;
        if (lane == 0) {
            __threadfence();
            ticket = atomicInc(&g_count, Bn - 1);
        }
        ticket = __shfl_sync(0xffffffffu, ticket, 0);
        if (ticket == Bn - 1) {
            float a = 0.f;
            #pragma unroll
            for (int i = 0; i < 8; ++i) a += g_losses[lane * 8 + i];
            #pragma unroll
            for (int o = 16; o > 0; o >>= 1) a += __shfl_xor_sync(0xffffffffu, a, o);
            if (lane == 0) gout[0] = a * (1.0f / (float)Bn);
        }
    }
}

extern "C" void kernel_launch(void* const* d_in, const int* in_sizes, int n_in,
                              void* d_out, int out_size)
{
    const float* q   = (const float*)d_in[0];
    const float* k   = (const float*)d_in[1];
    const float* v   = (const float*)d_in[2];
    const float* kcg = (const float*)d_in[3];
    const float* vcg = (const float*)d_in[4];

    cudaFuncSetAttribute(fml_kernel, cudaFuncAttributeMaxDynamicSharedMemorySize,
                         SMEM_FLOATS * (int)sizeof(float));
    fml_kernel<<<Bn, NT, SMEM_FLOATS * sizeof(float)>>>(q, k, v, kcg, vcg, (float*)d_out);
}